// round 1
// baseline (speedup 1.0000x reference)
#include <cuda_runtime.h>
#include <math.h>

#define B_ 2
#define S_ 1024
#define D_ 2048
#define H_ 16
#define G_ 4
#define DH_ 128
#define NQ_ 2048
#define NKV_ 512
#define NTOT_ 3072
#define MROWS_ 2048
#define NEG_BIG (-1e30f)

// ---------------- device scratch (allocation-free) ----------------
__device__ float g_Q[B_*H_*S_*DH_];   // [b,h,s,d]
__device__ float g_K[B_*G_*S_*DH_];   // [b,g,s,d]
__device__ float g_V[B_*G_*S_*DH_];   // [b,g,s,d]
__device__ float g_AO[B_*S_*H_*DH_];  // [b,s,h*128+d]

// ---------------- matryoshka reorder (closed form) ----------------
__device__ __forceinline__ int perm16(int h, int d) {
    return (d < 32) ? (h*32 + d)
         : (d < 64) ? (512 + h*32 + (d-32))
                    : (1024 + h*64 + (d-64));
}
__device__ __forceinline__ int perm4(int g, int d) {
    return (d < 32) ? (g*32 + d)
         : (d < 64) ? (128 + g*32 + (d-32))
                    : (256 + g*64 + (d-64));
}

// ================= Kernel 1: fused QKV projection GEMM =================
// A = x [2048 x 2048] row-major; N space = [Q(2048) | K(512) | V(512)]
// weight columns gathered through the reorder permutation.
__global__ __launch_bounds__(256)
void qkv_gemm_kernel(const float* __restrict__ x,
                     const float* __restrict__ Wq, const float* __restrict__ bq,
                     const float* __restrict__ Wk, const float* __restrict__ bk,
                     const float* __restrict__ Wv, const float* __restrict__ bv)
{
    __shared__ float As[16][128];
    __shared__ float Bs[16][128];
    const int tid = threadIdx.x;
    const int n0 = blockIdx.x * 128;
    const int m0 = blockIdx.y * 128;

    // B-tile load mapping (fixed column per thread)
    const int bcol = tid & 127;
    const int brow0 = (tid >> 7) * 8;
    const int nglob = n0 + bcol;
    const float* W; int ldw, src;
    if (nglob < NQ_)            { W = Wq; ldw = NQ_;  src = perm16(nglob >> 7, nglob & 127); }
    else if (nglob < NQ_+NKV_)  { int t = nglob - NQ_;       W = Wk; ldw = NKV_; src = perm4(t >> 7, t & 127); }
    else                        { int t = nglob - NQ_ - NKV_; W = Wv; ldw = NKV_; src = perm4(t >> 7, t & 127); }

    const int ty = tid >> 4, tx = tid & 15;
    float acc[8][8];
    #pragma unroll
    for (int i = 0; i < 8; i++)
        #pragma unroll
        for (int j = 0; j < 8; j++) acc[i][j] = 0.f;

    for (int k0 = 0; k0 < D_; k0 += 16) {
        #pragma unroll
        for (int it = 0; it < 2; it++) {
            int v = tid + it * 256;
            int row = v >> 2;
            int c4  = (v & 3) << 2;
            float4 a = *reinterpret_cast<const float4*>(x + (size_t)(m0 + row) * D_ + k0 + c4);
            As[c4+0][row] = a.x; As[c4+1][row] = a.y; As[c4+2][row] = a.z; As[c4+3][row] = a.w;
        }
        #pragma unroll
        for (int i = 0; i < 8; i++)
            Bs[brow0 + i][bcol] = W[(size_t)(k0 + brow0 + i) * ldw + src];
        __syncthreads();

        #pragma unroll
        for (int kk = 0; kk < 16; kk++) {
            float4 a0 = *reinterpret_cast<const float4*>(&As[kk][ty*8]);
            float4 a1 = *reinterpret_cast<const float4*>(&As[kk][ty*8+4]);
            float4 b0 = *reinterpret_cast<const float4*>(&Bs[kk][tx*8]);
            float4 b1 = *reinterpret_cast<const float4*>(&Bs[kk][tx*8+4]);
            float a[8] = {a0.x,a0.y,a0.z,a0.w,a1.x,a1.y,a1.z,a1.w};
            float b[8] = {b0.x,b0.y,b0.z,b0.w,b1.x,b1.y,b1.z,b1.w};
            #pragma unroll
            for (int i = 0; i < 8; i++)
                #pragma unroll
                for (int j = 0; j < 8; j++)
                    acc[i][j] = fmaf(a[i], b[j], acc[i][j]);
        }
        __syncthreads();
    }

    // epilogue: bias + scatter to head-major layouts
    #pragma unroll
    for (int j = 0; j < 8; j++) {
        int nn = n0 + tx*8 + j;
        if (nn < NQ_) {
            int h = nn >> 7, d = nn & 127;
            float bias = bq[perm16(h, d)];
            #pragma unroll
            for (int i = 0; i < 8; i++) {
                int m = m0 + ty*8 + i;
                int bb = m >> 10, s = m & 1023;
                g_Q[(((bb*H_ + h)*S_) + s)*DH_ + d] = acc[i][j] + bias;
            }
        } else if (nn < NQ_ + NKV_) {
            int t = nn - NQ_;
            int g = t >> 7, d = t & 127;
            float bias = bk[perm4(g, d)];
            #pragma unroll
            for (int i = 0; i < 8; i++) {
                int m = m0 + ty*8 + i;
                int bb = m >> 10, s = m & 1023;
                g_K[(((bb*G_ + g)*S_) + s)*DH_ + d] = acc[i][j] + bias;
            }
        } else {
            int t = nn - NQ_ - NKV_;
            int g = t >> 7, d = t & 127;
            float bias = bv[perm4(g, d)];
            #pragma unroll
            for (int i = 0; i < 8; i++) {
                int m = m0 + ty*8 + i;
                int bb = m >> 10, s = m & 1023;
                g_V[(((bb*G_ + g)*S_) + s)*DH_ + d] = acc[i][j] + bias;
            }
        }
    }
}

// ================= Kernel 2: 3-level matryoshka flash attention =================
// One CTA = (b, h, 64-row q tile). Cumulative scores shared across levels.
template<int DCOLS>
__device__ __forceinline__ void level_update(
    float (*sc)[4], float scale, float* m, float* l, float* o,
    int q0, int k0, int ty, int tx, float* sP, const float* sV, int dbase)
{
    // scale + causal mask + row max
    float mx[4];
    #pragma unroll
    for (int i = 0; i < 4; i++) {
        float rowm = NEG_BIG;
        #pragma unroll
        for (int j = 0; j < 4; j++) {
            float t = sc[i][j] * scale;
            if (k0 + 4*tx + j > q0 + 4*ty + i) t = NEG_BIG;
            sc[i][j] = t;
            rowm = fmaxf(rowm, t);
        }
        mx[i] = rowm;
    }
    #pragma unroll
    for (int off = 8; off >= 1; off >>= 1)
        #pragma unroll
        for (int i = 0; i < 4; i++)
            mx[i] = fmaxf(mx[i], __shfl_xor_sync(0xffffffffu, mx[i], off));

    float alpha[4], rs[4];
    #pragma unroll
    for (int i = 0; i < 4; i++) {
        float mn = fmaxf(m[i], mx[i]);
        alpha[i] = __expf(m[i] - mn);
        m[i] = mn;
        float s = 0.f;
        #pragma unroll
        for (int j = 0; j < 4; j++) {
            float p = __expf(sc[i][j] - mn);
            sc[i][j] = p;
            s += p;
        }
        rs[i] = s;
    }
    #pragma unroll
    for (int off = 8; off >= 1; off >>= 1)
        #pragma unroll
        for (int i = 0; i < 4; i++)
            rs[i] += __shfl_xor_sync(0xffffffffu, rs[i], off);
    #pragma unroll
    for (int i = 0; i < 4; i++)
        l[i] = l[i]*alpha[i] + rs[i];

    // stage P tile
    #pragma unroll
    for (int i = 0; i < 4; i++)
        #pragma unroll
        for (int j = 0; j < 4; j++)
            sP[(4*ty+i)*68 + 4*tx + j] = sc[i][j];
    __syncthreads();

    // rescale O, then O += P @ V[:, dbase + DCOLS*tx ...]
    #pragma unroll
    for (int i = 0; i < 4; i++)
        #pragma unroll
        for (int c = 0; c < DCOLS; c++)
            o[i*DCOLS + c] *= alpha[i];

    const int dcol = dbase + DCOLS*tx;
    #pragma unroll 4
    for (int k4 = 0; k4 < 16; k4++) {
        float v[4][DCOLS];
        #pragma unroll
        for (int u = 0; u < 4; u++) {
            if (DCOLS == 2) {
                float2 t = *reinterpret_cast<const float2*>(&sV[(k4*4+u)*128 + dcol]);
                v[u][0] = t.x; v[u][1] = t.y;
            } else {
                float4 t = *reinterpret_cast<const float4*>(&sV[(k4*4+u)*128 + dcol]);
                v[u][0] = t.x; v[u][1] = t.y; v[u][2] = t.z; v[u][3] = t.w;
            }
        }
        #pragma unroll
        for (int i = 0; i < 4; i++) {
            float4 p = *reinterpret_cast<const float4*>(&sP[(4*ty+i)*68 + k4*4]);
            float pw[4] = {p.x, p.y, p.z, p.w};
            #pragma unroll
            for (int u = 0; u < 4; u++)
                #pragma unroll
                for (int c = 0; c < DCOLS; c++)
                    o[i*DCOLS + c] = fmaf(pw[u], v[u][c], o[i*DCOLS + c]);
        }
    }
    __syncthreads();
}

__global__ __launch_bounds__(256)
void attn_kernel()
{
    extern __shared__ float sm[];
    float* sQ  = sm;                 // [64][128]
    float* sKt = sQ  + 64*128;       // [128][64] transposed, XOR-swizzled
    float* sV  = sKt + 128*64;       // [64][128]
    float* sP  = sV  + 64*128;       // [64] x pitch 68

    const int qt = blockIdx.x, h = blockIdx.y, b = blockIdx.z;
    const int g  = h >> 2;           // GQA: 4 heads per group
    const float* Qp = g_Q + ((size_t)(b*H_ + h) * S_) * DH_;
    const float* Kp = g_K + ((size_t)(b*G_ + g) * S_) * DH_;
    const float* Vp = g_V + ((size_t)(b*G_ + g) * S_) * DH_;
    const int q0 = qt * 64;
    const int tid = threadIdx.x;
    const int ty = tid >> 4, tx = tid & 15;

    // load Q tile
    for (int v = tid; v < 64*128/4; v += 256)
        reinterpret_cast<float4*>(sQ)[v] =
            reinterpret_cast<const float4*>(Qp + (size_t)q0 * DH_)[v];

    float m_[3][4], l_[3][4];
    float o0[8], o1[8], o2[16];
    #pragma unroll
    for (int L = 0; L < 3; L++)
        #pragma unroll
        for (int i = 0; i < 4; i++) { m_[L][i] = NEG_BIG; l_[L][i] = 0.f; }
    #pragma unroll
    for (int i = 0; i < 8; i++)  { o0[i] = 0.f; o1[i] = 0.f; }
    #pragma unroll
    for (int i = 0; i < 16; i++) o2[i] = 0.f;

    const float scale0 = 0.17677669529663687f;   // 1/sqrt(32)
    const float scale1 = 0.125f;                 // 1/sqrt(64)
    const float scale2 = 0.08838834764831843f;   // 1/sqrt(128)

    for (int kt = 0; kt <= qt; kt++) {
        const int k0 = kt * 64;

        // load K transposed with XOR swizzle: sKt[d*64 + (r ^ ((d&15)<<2))]
        {
            int c  = tid & 127;
            int r0 = (tid >> 7) * 32;
            const float* kg = Kp + (size_t)k0 * DH_ + c;
            int sw = (c & 15) << 2;
            #pragma unroll 8
            for (int rr = 0; rr < 32; rr++)
                sKt[c*64 + ((r0 + rr) ^ sw)] = kg[(size_t)(r0 + rr) * DH_];
        }
        // load V row-major
        for (int v = tid; v < 64*128/4; v += 256)
            reinterpret_cast<float4*>(sV)[v] =
                reinterpret_cast<const float4*>(Vp + (size_t)k0 * DH_)[v];
        __syncthreads();

        // cumulative scores: s0 = d[0:32), s1 = d[32:64), s2 = d[64:128)
        float s0[4][4], s1[4][4], s2[4][4];
        #pragma unroll
        for (int i = 0; i < 4; i++)
            #pragma unroll
            for (int j = 0; j < 4; j++) { s0[i][j]=0.f; s1[i][j]=0.f; s2[i][j]=0.f; }

        #pragma unroll 4
        for (int dd = 0; dd < 8; dd++) {           // level 0 segment
            float aq[4][4];
            #pragma unroll
            for (int i = 0; i < 4; i++) {
                float4 t = *reinterpret_cast<const float4*>(&sQ[(4*ty+i)*128 + dd*4]);
                aq[i][0]=t.x; aq[i][1]=t.y; aq[i][2]=t.z; aq[i][3]=t.w;
            }
            #pragma unroll
            for (int u = 0; u < 4; u++) {
                int d = dd*4 + u;
                float4 t = *reinterpret_cast<const float4*>(&sKt[d*64 + ((4*tx) ^ ((d & 15) << 2))]);
                float bw[4] = {t.x, t.y, t.z, t.w};
                #pragma unroll
                for (int i = 0; i < 4; i++)
                    #pragma unroll
                    for (int j = 0; j < 4; j++)
                        s0[i][j] = fmaf(aq[i][u], bw[j], s0[i][j]);
            }
        }
        #pragma unroll 4
        for (int dd = 8; dd < 16; dd++) {          // level 1 segment
            float aq[4][4];
            #pragma unroll
            for (int i = 0; i < 4; i++) {
                float4 t = *reinterpret_cast<const float4*>(&sQ[(4*ty+i)*128 + dd*4]);
                aq[i][0]=t.x; aq[i][1]=t.y; aq[i][2]=t.z; aq[i][3]=t.w;
            }
            #pragma unroll
            for (int u = 0; u < 4; u++) {
                int d = dd*4 + u;
                float4 t = *reinterpret_cast<const float4*>(&sKt[d*64 + ((4*tx) ^ ((d & 15) << 2))]);
                float bw[4] = {t.x, t.y, t.z, t.w};
                #pragma unroll
                for (int i = 0; i < 4; i++)
                    #pragma unroll
                    for (int j = 0; j < 4; j++)
                        s1[i][j] = fmaf(aq[i][u], bw[j], s1[i][j]);
            }
        }
        #pragma unroll 4
        for (int dd = 16; dd < 32; dd++) {         // level 2 segment
            float aq[4][4];
            #pragma unroll
            for (int i = 0; i < 4; i++) {
                float4 t = *reinterpret_cast<const float4*>(&sQ[(4*ty+i)*128 + dd*4]);
                aq[i][0]=t.x; aq[i][1]=t.y; aq[i][2]=t.z; aq[i][3]=t.w;
            }
            #pragma unroll
            for (int u = 0; u < 4; u++) {
                int d = dd*4 + u;
                float4 t = *reinterpret_cast<const float4*>(&sKt[d*64 + ((4*tx) ^ ((d & 15) << 2))]);
                float bw[4] = {t.x, t.y, t.z, t.w};
                #pragma unroll
                for (int i = 0; i < 4; i++)
                    #pragma unroll
                    for (int j = 0; j < 4; j++)
                        s2[i][j] = fmaf(aq[i][u], bw[j], s2[i][j]);
            }
        }
        // cumulative sums
        #pragma unroll
        for (int i = 0; i < 4; i++)
            #pragma unroll
            for (int j = 0; j < 4; j++) {
                s1[i][j] += s0[i][j];
                s2[i][j] += s1[i][j];
            }

        level_update<2>(s0, scale0, m_[0], l_[0], o0, q0, k0, ty, tx, sP, sV, 0);
        level_update<2>(s1, scale1, m_[1], l_[1], o1, q0, k0, ty, tx, sP, sV, 32);
        level_update<4>(s2, scale2, m_[2], l_[2], o2, q0, k0, ty, tx, sP, sV, 64);
    }

    // epilogue: normalize + write [b, s, h*128 + d]
    #pragma unroll
    for (int i = 0; i < 4; i++) {
        int qi = q0 + 4*ty + i;
        float* outp = g_AO + ((size_t)(b*S_ + qi)) * (H_*DH_) + h*DH_;
        float i0 = 1.f / l_[0][i], i1 = 1.f / l_[1][i], i2 = 1.f / l_[2][i];
        outp[2*tx]        = o0[i*2+0]*i0;
        outp[2*tx+1]      = o0[i*2+1]*i0;
        outp[32 + 2*tx]   = o1[i*2+0]*i1;
        outp[32 + 2*tx+1] = o1[i*2+1]*i1;
        outp[64 + 4*tx+0] = o2[i*4+0]*i2;
        outp[64 + 4*tx+1] = o2[i*4+1]*i2;
        outp[64 + 4*tx+2] = o2[i*4+2]*i2;
        outp[64 + 4*tx+3] = o2[i*4+3]*i2;
    }
}

// ================= Kernel 3: output projection GEMM =================
// out = AO @ Wo[perm16-rows, :] + bo
__global__ __launch_bounds__(256)
void out_gemm_kernel(const float* __restrict__ Wo, const float* __restrict__ bo,
                     float* __restrict__ out)
{
    __shared__ float As[16][128];
    __shared__ float Bs[16][128];
    const int tid = threadIdx.x;
    const int n0 = blockIdx.x * 128;
    const int m0 = blockIdx.y * 128;

    const int bcol = tid & 127;
    const int brow0 = (tid >> 7) * 8;
    const int ty = tid >> 4, tx = tid & 15;

    float acc[8][8];
    #pragma unroll
    for (int i = 0; i < 8; i++)
        #pragma unroll
        for (int j = 0; j < 8; j++) acc[i][j] = 0.f;

    for (int k0 = 0; k0 < D_; k0 += 16) {
        #pragma unroll
        for (int it = 0; it < 2; it++) {
            int v = tid + it * 256;
            int row = v >> 2;
            int c4  = (v & 3) << 2;
            float4 a = *reinterpret_cast<const float4*>(g_AO + (size_t)(m0 + row) * D_ + k0 + c4);
            As[c4+0][row] = a.x; As[c4+1][row] = a.y; As[c4+2][row] = a.z; As[c4+3][row] = a.w;
        }
        #pragma unroll
        for (int i = 0; i < 8; i++) {
            int kidx = k0 + brow0 + i;
            int srcrow = perm16(kidx >> 7, kidx & 127);
            Bs[brow0 + i][bcol] = Wo[(size_t)srcrow * D_ + n0 + bcol];
        }
        __syncthreads();

        #pragma unroll
        for (int kk = 0; kk < 16; kk++) {
            float4 a0 = *reinterpret_cast<const float4*>(&As[kk][ty*8]);
            float4 a1 = *reinterpret_cast<const float4*>(&As[kk][ty*8+4]);
            float4 b0 = *reinterpret_cast<const float4*>(&Bs[kk][tx*8]);
            float4 b1 = *reinterpret_cast<const float4*>(&Bs[kk][tx*8+4]);
            float a[8] = {a0.x,a0.y,a0.z,a0.w,a1.x,a1.y,a1.z,a1.w};
            float b[8] = {b0.x,b0.y,b0.z,b0.w,b1.x,b1.y,b1.z,b1.w};
            #pragma unroll
            for (int i = 0; i < 8; i++)
                #pragma unroll
                for (int j = 0; j < 8; j++)
                    acc[i][j] = fmaf(a[i], b[j], acc[i][j]);
        }
        __syncthreads();
    }

    #pragma unroll
    for (int j = 0; j < 8; j++) {
        int nn = n0 + tx*8 + j;
        float bias = bo[nn];
        #pragma unroll
        for (int i = 0; i < 8; i++) {
            int m = m0 + ty*8 + i;
            out[(size_t)m * D_ + nn] = acc[i][j] + bias;
        }
    }
}

// ================= launch =================
extern "C" void kernel_launch(void* const* d_in, const int* in_sizes, int n_in,
                              void* d_out, int out_size)
{
    (void)in_sizes; (void)n_in; (void)out_size;
    const float* x  = (const float*)d_in[0];
    // d_in[1] = mask (always causal tril per problem setup; applied analytically)
    const float* Wq = (const float*)d_in[2];
    const float* bq = (const float*)d_in[3];
    const float* Wk = (const float*)d_in[4];
    const float* bk = (const float*)d_in[5];
    const float* Wv = (const float*)d_in[6];
    const float* bv = (const float*)d_in[7];
    const float* Wo = (const float*)d_in[8];
    const float* bo = (const float*)d_in[9];
    float* out = (float*)d_out;

    qkv_gemm_kernel<<<dim3(NTOT_/128, MROWS_/128), 256>>>(x, Wq, bq, Wk, bk, Wv, bv);

    size_t smem = (size_t)(64*128 + 128*64 + 64*128 + 64*68) * sizeof(float);
    cudaFuncSetAttribute(attn_kernel, cudaFuncAttributeMaxDynamicSharedMemorySize, (int)smem);
    attn_kernel<<<dim3(S_/64, H_, B_), 256, smem>>>();

    out_gemm_kernel<<<dim3(D_/128, MROWS_/128), 256>>>(Wo, bo, out);
}

// round 4
// speedup vs baseline: 1.9318x; 1.9318x over previous
#include <cuda_runtime.h>
#include <cuda_bf16.h>
#include <stdint.h>
#include <cstdint>
#include <math.h>

#define B_ 2
#define S_ 1024
#define D_ 2048
#define H_ 16
#define G_ 4
#define DH_ 128
#define NQ_ 2048
#define NKV_ 512
#define NTOT_ 3072
#define MROWS_ 2048
#define NEG_BIG (-1e30f)

// GEMM tiling
#define KC 32                 // k per stage
#define PITCHB 80             // bytes per smem row (40 bf16) — conflict-free ldmatrix
#define TILE_B (128 * PITCHB) // 10240 B per operand tile
#define STAGE_B (4 * TILE_B)  // Ah, Al, Bh, Bl

// ---------------- device scratch ----------------
__device__ float g_Q[B_*H_*S_*DH_];
__device__ float g_K[B_*G_*S_*DH_];
__device__ float g_V[B_*G_*S_*DH_];
__device__ __nv_bfloat16 g_xh[MROWS_*D_];
__device__ __nv_bfloat16 g_xl[MROWS_*D_];
__device__ __nv_bfloat16 g_Wth[NTOT_*D_];   // W_qkv^T, perm folded: [n][k]
__device__ __nv_bfloat16 g_Wtl[NTOT_*D_];
__device__ __nv_bfloat16 g_Woth[D_*D_];     // Wo^T row-perm folded: [n][k]
__device__ __nv_bfloat16 g_Wotl[D_*D_];
__device__ __nv_bfloat16 g_AOh[MROWS_*D_];
__device__ __nv_bfloat16 g_AOl[MROWS_*D_];

// ---------------- matryoshka reorder ----------------
__device__ __forceinline__ int perm16(int h, int d) {
    return (d < 32) ? (h*32 + d)
         : (d < 64) ? (512 + h*32 + (d-32))
                    : (1024 + h*64 + (d-64));
}
__device__ __forceinline__ int perm4(int g, int d) {
    return (d < 32) ? (g*32 + d)
         : (d < 64) ? (128 + g*32 + (d-32))
                    : (256 + g*64 + (d-64));
}

// ---------------- PTX helpers ----------------
__device__ __forceinline__ uint32_t smem_u32(const void* p) {
    uint32_t a;
    asm("{ .reg .u64 t; cvta.to.shared.u64 t, %1; cvt.u32.u64 %0, t; }" : "=r"(a) : "l"(p));
    return a;
}
__device__ __forceinline__ void cp_async16(uint32_t d, const void* g) {
    asm volatile("cp.async.cg.shared.global [%0], [%1], 16;" :: "r"(d), "l"(g));
}
__device__ __forceinline__ void ldsm4(uint32_t* r, uint32_t addr) {
    asm volatile("ldmatrix.sync.aligned.m8n8.x4.shared.b16 {%0,%1,%2,%3}, [%4];"
                 : "=r"(r[0]), "=r"(r[1]), "=r"(r[2]), "=r"(r[3]) : "r"(addr));
}
__device__ __forceinline__ void mma16816(float* c, const uint32_t* a, const uint32_t* b) {
    asm volatile(
        "mma.sync.aligned.m16n8k16.row.col.f32.bf16.bf16.f32 "
        "{%0,%1,%2,%3}, {%4,%5,%6,%7}, {%8,%9}, {%0,%1,%2,%3};"
        : "+f"(c[0]), "+f"(c[1]), "+f"(c[2]), "+f"(c[3])
        : "r"(a[0]), "r"(a[1]), "r"(a[2]), "r"(a[3]), "r"(b[0]), "r"(b[1]));
}
__device__ __forceinline__ void bf16_split(float v, __nv_bfloat16& h, __nv_bfloat16& l) {
    h = __float2bfloat16(v);
    l = __float2bfloat16(v - __bfloat162float(h));
}

// ================= converters =================
__global__ __launch_bounds__(256) void convx_kernel(const float* __restrict__ x) {
    int i = blockIdx.x * 256 + threadIdx.x;      // per float4
    float4 v = reinterpret_cast<const float4*>(x)[i];
    __nv_bfloat16 h0,l0,h1,l1,h2,l2,h3,l3;
    bf16_split(v.x,h0,l0); bf16_split(v.y,h1,l1); bf16_split(v.z,h2,l2); bf16_split(v.w,h3,l3);
    __nv_bfloat162* ph = reinterpret_cast<__nv_bfloat162*>(g_xh);
    __nv_bfloat162* pl = reinterpret_cast<__nv_bfloat162*>(g_xl);
    ph[2*i]   = __nv_bfloat162(h0,h1); ph[2*i+1] = __nv_bfloat162(h2,h3);
    pl[2*i]   = __nv_bfloat162(l0,l1); pl[2*i+1] = __nv_bfloat162(l2,l3);
}

__global__ __launch_bounds__(256)
void tconv_qkv_kernel(const float* __restrict__ Wq, const float* __restrict__ Wk,
                      const float* __restrict__ Wv) {
    __shared__ float ts[64][65];
    const int tid = threadIdx.x;
    const int n0 = blockIdx.x * 64, k0 = blockIdx.y * 64;
    for (int idx = tid; idx < 4096; idx += 256) {
        int kk = idx >> 6, nn = idx & 63;
        int n = n0 + nn;
        const float* W; int ldw, src;
        if (n < NQ_)            { W = Wq; ldw = NQ_;  src = perm16(n >> 7, n & 127); }
        else if (n < NQ_+NKV_)  { int t = n - NQ_;        W = Wk; ldw = NKV_; src = perm4(t >> 7, t & 127); }
        else                    { int t = n - NQ_ - NKV_; W = Wv; ldw = NKV_; src = perm4(t >> 7, t & 127); }
        ts[kk][nn] = W[(size_t)(k0 + kk) * ldw + src];
    }
    __syncthreads();
    for (int idx = tid; idx < 4096; idx += 256) {
        int nn = idx >> 6, kk = idx & 63;
        __nv_bfloat16 h, l;
        bf16_split(ts[kk][nn], h, l);
        size_t o = (size_t)(n0 + nn) * D_ + k0 + kk;
        g_Wth[o] = h; g_Wtl[o] = l;
    }
}

__global__ __launch_bounds__(256)
void tconv_wo_kernel(const float* __restrict__ Wo) {
    __shared__ float ts[64][65];
    const int tid = threadIdx.x;
    const int n0 = blockIdx.x * 64, k0 = blockIdx.y * 64;
    for (int idx = tid; idx < 4096; idx += 256) {
        int kk = idx >> 6, nn = idx & 63;
        int k = k0 + kk;
        int srcrow = perm16(k >> 7, k & 127);
        ts[kk][nn] = Wo[(size_t)srcrow * D_ + n0 + nn];
    }
    __syncthreads();
    for (int idx = tid; idx < 4096; idx += 256) {
        int nn = idx >> 6, kk = idx & 63;
        __nv_bfloat16 h, l;
        bf16_split(ts[kk][nn], h, l);
        size_t o = (size_t)(n0 + nn) * D_ + k0 + kk;
        g_Woth[o] = h; g_Wotl[o] = l;
    }
}

// ================= mma.sync bf16x3 GEMM =================
// MODE 0: QKV (A=x hi/lo, B=Wt hi/lo, scatter to g_Q/K/V with bias)
// MODE 1: out (A=AO hi/lo, B=Wot hi/lo, write d_out with bias; bq carries bo)
template<int MODE>
__global__ __launch_bounds__(256, 1)
void gemm_mma_kernel(const __nv_bfloat16* __restrict__ Ah, const __nv_bfloat16* __restrict__ Al,
                     const __nv_bfloat16* __restrict__ Bh, const __nv_bfloat16* __restrict__ Bl,
                     float* __restrict__ outp,
                     const float* __restrict__ bq, const float* __restrict__ bk,
                     const float* __restrict__ bv)
{
    extern __shared__ char smem[];
    const uint32_t sb = smem_u32(smem);
    float* sBias = reinterpret_cast<float*>(smem + 2 * STAGE_B);

    const int tid  = threadIdx.x;
    const int lane = tid & 31;
    const int wid  = tid >> 5;
    const int wm = wid >> 1;      // 0..3 -> m offset 32*wm
    const int wn = wid & 1;       // 0..1 -> n offset 64*wn
    const int n0 = blockIdx.x * 128;
    const int m0 = blockIdx.y * 128;
    const int NK = D_ / KC;       // 64

    if (tid < 128) {
        int n = n0 + tid;
        float b;
        if (MODE == 0) {
            if (n < NQ_)            b = bq[perm16(n >> 7, n & 127)];
            else if (n < NQ_+NKV_)  { int t = n - NQ_;        b = bk[perm4(t >> 7, t & 127)]; }
            else                    { int t = n - NQ_ - NKV_; b = bv[perm4(t >> 7, t & 127)]; }
        } else b = bq[n];
        sBias[tid] = b;
    }

    const __nv_bfloat16* srcs[4] = {
        Ah + (size_t)m0 * D_, Al + (size_t)m0 * D_,
        Bh + (size_t)n0 * D_, Bl + (size_t)n0 * D_ };

    auto load_stage = [&](int chunk) {
        const uint32_t st = sb + (chunk & 1) * STAGE_B;
        const int k0 = chunk * KC;
        #pragma unroll
        for (int t = 0; t < 4; t++) {
            const __nv_bfloat16* s = srcs[t];
            const uint32_t tb = st + t * TILE_B;
            #pragma unroll
            for (int it = 0; it < 2; it++) {
                int idx = tid + it * 256;
                int r = idx >> 2, c = idx & 3;
                cp_async16(tb + r * PITCHB + c * 16, s + (size_t)r * D_ + k0 + c * 8);
            }
        }
        asm volatile("cp.async.commit_group;" ::: "memory");
    };

    float acc[2][8][4];
    #pragma unroll
    for (int mi = 0; mi < 2; mi++)
        #pragma unroll
        for (int ni = 0; ni < 8; ni++)
            #pragma unroll
            for (int q = 0; q < 4; q++) acc[mi][ni][q] = 0.f;

    const int mat = lane >> 3, rin = lane & 7;
    const int arow = wm*32 + (mat & 1)*8 + rin;       // + mi*16
    const uint32_t acol = (uint32_t)(mat >> 1) * 16;  // + kk*32
    const int brow = wn*64 + (mat >> 1)*8 + rin;      // + nb*16
    const uint32_t bcol = (uint32_t)(mat & 1) * 16;   // + kk*32

    load_stage(0);
    load_stage(1);

    for (int i = 0; i < NK; i++) {
        if (i == NK - 1) asm volatile("cp.async.wait_group 0;" ::: "memory");
        else             asm volatile("cp.async.wait_group 1;" ::: "memory");
        __syncthreads();

        const uint32_t st = sb + (i & 1) * STAGE_B;
        const uint32_t aH = st, aL = st + TILE_B, bH = st + 2*TILE_B, bL = st + 3*TILE_B;

        #pragma unroll
        for (int kk = 0; kk < 2; kk++) {
            uint32_t ah[2][4], al[2][4];
            #pragma unroll
            for (int mi = 0; mi < 2; mi++) {
                uint32_t off = (uint32_t)(arow + mi*16) * PITCHB + acol + kk*32;
                ldsm4(ah[mi], aH + off);
                ldsm4(al[mi], aL + off);
            }
            uint32_t bhf[8][2], blf[8][2];
            #pragma unroll
            for (int nb = 0; nb < 4; nb++) {
                uint32_t off = (uint32_t)(brow + nb*16) * PITCHB + bcol + kk*32;
                uint32_t r4[4];
                ldsm4(r4, bH + off);
                bhf[2*nb][0] = r4[0]; bhf[2*nb][1] = r4[1];
                bhf[2*nb+1][0] = r4[2]; bhf[2*nb+1][1] = r4[3];
                ldsm4(r4, bL + off);
                blf[2*nb][0] = r4[0]; blf[2*nb][1] = r4[1];
                blf[2*nb+1][0] = r4[2]; blf[2*nb+1][1] = r4[3];
            }
            #pragma unroll
            for (int mi = 0; mi < 2; mi++)
                #pragma unroll
                for (int ni = 0; ni < 8; ni++) {
                    mma16816(acc[mi][ni], ah[mi], bhf[ni]);
                    mma16816(acc[mi][ni], al[mi], bhf[ni]);
                    mma16816(acc[mi][ni], ah[mi], blf[ni]);
                }
        }
        __syncthreads();
        if (i + 2 < NK) load_stage(i + 2);
    }

    // ---------- epilogue: register fragments -> global with bias ----------
    const int g = lane >> 2, tig = lane & 3;
    #pragma unroll
    for (int mi = 0; mi < 2; mi++)
        #pragma unroll
        for (int ni = 0; ni < 8; ni++) {
            int col = wn*64 + ni*8 + tig*2;
            float b0 = sBias[col], b1 = sBias[col + 1];
            #pragma unroll
            for (int half = 0; half < 2; half++) {
                int row = m0 + wm*32 + mi*16 + g + half*8;
                float2 v = make_float2(acc[mi][ni][half*2+0] + b0,
                                       acc[mi][ni][half*2+1] + b1);
                if (MODE == 0) {
                    int bb = row >> 10, s = row & 1023;
                    float* dst;
                    if (n0 < NQ_)           { int h = n0 >> 7;              dst = g_Q + ((size_t)((bb*H_ + h)*S_ + s))*DH_; }
                    else if (n0 < NQ_+NKV_) { int gg = (n0 - NQ_) >> 7;     dst = g_K + ((size_t)((bb*G_ + gg)*S_ + s))*DH_; }
                    else                    { int gg = (n0 - NQ_-NKV_) >> 7; dst = g_V + ((size_t)((bb*G_ + gg)*S_ + s))*DH_; }
                    *reinterpret_cast<float2*>(dst + col) = v;
                } else {
                    *reinterpret_cast<float2*>(outp + (size_t)row * D_ + n0 + col) = v;
                }
            }
        }
}

// ================= Kernel 2: 3-level matryoshka flash attention =================
template<int DCOLS>
__device__ __forceinline__ void level_update(
    float (*sc)[4], float scale, float* m, float* l, float* o,
    int q0, int k0, int ty, int tx, float* sP, const float* sV, int dbase)
{
    float mx[4];
    #pragma unroll
    for (int i = 0; i < 4; i++) {
        float rowm = NEG_BIG;
        #pragma unroll
        for (int j = 0; j < 4; j++) {
            float t = sc[i][j] * scale;
            if (k0 + 4*tx + j > q0 + 4*ty + i) t = NEG_BIG;
            sc[i][j] = t;
            rowm = fmaxf(rowm, t);
        }
        mx[i] = rowm;
    }
    #pragma unroll
    for (int off = 8; off >= 1; off >>= 1)
        #pragma unroll
        for (int i = 0; i < 4; i++)
            mx[i] = fmaxf(mx[i], __shfl_xor_sync(0xffffffffu, mx[i], off));

    float alpha[4], rs[4];
    #pragma unroll
    for (int i = 0; i < 4; i++) {
        float mn = fmaxf(m[i], mx[i]);
        alpha[i] = __expf(m[i] - mn);
        m[i] = mn;
        float s = 0.f;
        #pragma unroll
        for (int j = 0; j < 4; j++) {
            float p = __expf(sc[i][j] - mn);
            sc[i][j] = p;
            s += p;
        }
        rs[i] = s;
    }
    #pragma unroll
    for (int off = 8; off >= 1; off >>= 1)
        #pragma unroll
        for (int i = 0; i < 4; i++)
            rs[i] += __shfl_xor_sync(0xffffffffu, rs[i], off);
    #pragma unroll
    for (int i = 0; i < 4; i++)
        l[i] = l[i]*alpha[i] + rs[i];

    #pragma unroll
    for (int i = 0; i < 4; i++)
        #pragma unroll
        for (int j = 0; j < 4; j++)
            sP[(4*ty+i)*68 + 4*tx + j] = sc[i][j];
    __syncthreads();

    #pragma unroll
    for (int i = 0; i < 4; i++)
        #pragma unroll
        for (int c = 0; c < DCOLS; c++)
            o[i*DCOLS + c] *= alpha[i];

    const int dcol = dbase + DCOLS*tx;
    #pragma unroll 4
    for (int k4 = 0; k4 < 16; k4++) {
        float v[4][DCOLS];
        #pragma unroll
        for (int u = 0; u < 4; u++) {
            if (DCOLS == 2) {
                float2 t = *reinterpret_cast<const float2*>(&sV[(k4*4+u)*128 + dcol]);
                v[u][0] = t.x; v[u][1] = t.y;
            } else {
                float4 t = *reinterpret_cast<const float4*>(&sV[(k4*4+u)*128 + dcol]);
                v[u][0] = t.x; v[u][1] = t.y; v[u][2] = t.z; v[u][3] = t.w;
            }
        }
        #pragma unroll
        for (int i = 0; i < 4; i++) {
            float4 p = *reinterpret_cast<const float4*>(&sP[(4*ty+i)*68 + k4*4]);
            float pw[4] = {p.x, p.y, p.z, p.w};
            #pragma unroll
            for (int u = 0; u < 4; u++)
                #pragma unroll
                for (int c = 0; c < DCOLS; c++)
                    o[i*DCOLS + c] = fmaf(pw[u], v[u][c], o[i*DCOLS + c]);
        }
    }
    __syncthreads();
}

__global__ __launch_bounds__(256)
void attn_kernel()
{
    extern __shared__ float sm[];
    float* sQ  = sm;
    float* sKt = sQ  + 64*128;
    float* sV  = sKt + 128*64;
    float* sP  = sV  + 64*128;

    const int qt = blockIdx.x, h = blockIdx.y, b = blockIdx.z;
    const int g  = h >> 2;
    const float* Qp = g_Q + ((size_t)(b*H_ + h) * S_) * DH_;
    const float* Kp = g_K + ((size_t)(b*G_ + g) * S_) * DH_;
    const float* Vp = g_V + ((size_t)(b*G_ + g) * S_) * DH_;
    const int q0 = qt * 64;
    const int tid = threadIdx.x;
    const int ty = tid >> 4, tx = tid & 15;

    for (int v = tid; v < 64*128/4; v += 256)
        reinterpret_cast<float4*>(sQ)[v] =
            reinterpret_cast<const float4*>(Qp + (size_t)q0 * DH_)[v];

    float m_[3][4], l_[3][4];
    float o0[8], o1[8], o2[16];
    #pragma unroll
    for (int L = 0; L < 3; L++)
        #pragma unroll
        for (int i = 0; i < 4; i++) { m_[L][i] = NEG_BIG; l_[L][i] = 0.f; }
    #pragma unroll
    for (int i = 0; i < 8; i++)  { o0[i] = 0.f; o1[i] = 0.f; }
    #pragma unroll
    for (int i = 0; i < 16; i++) o2[i] = 0.f;

    const float scale0 = 0.17677669529663687f;
    const float scale1 = 0.125f;
    const float scale2 = 0.08838834764831843f;

    for (int kt = 0; kt <= qt; kt++) {
        const int k0 = kt * 64;
        {
            int c  = tid & 127;
            int r0 = (tid >> 7) * 32;
            const float* kg = Kp + (size_t)k0 * DH_ + c;
            int sw = (c & 15) << 2;
            #pragma unroll 8
            for (int rr = 0; rr < 32; rr++)
                sKt[c*64 + ((r0 + rr) ^ sw)] = kg[(size_t)(r0 + rr) * DH_];
        }
        for (int v = tid; v < 64*128/4; v += 256)
            reinterpret_cast<float4*>(sV)[v] =
                reinterpret_cast<const float4*>(Vp + (size_t)k0 * DH_)[v];
        __syncthreads();

        float s0[4][4], s1[4][4], s2[4][4];
        #pragma unroll
        for (int i = 0; i < 4; i++)
            #pragma unroll
            for (int j = 0; j < 4; j++) { s0[i][j]=0.f; s1[i][j]=0.f; s2[i][j]=0.f; }

        #pragma unroll 4
        for (int dd = 0; dd < 8; dd++) {
            float aq[4][4];
            #pragma unroll
            for (int i = 0; i < 4; i++) {
                float4 t = *reinterpret_cast<const float4*>(&sQ[(4*ty+i)*128 + dd*4]);
                aq[i][0]=t.x; aq[i][1]=t.y; aq[i][2]=t.z; aq[i][3]=t.w;
            }
            #pragma unroll
            for (int u = 0; u < 4; u++) {
                int d = dd*4 + u;
                float4 t = *reinterpret_cast<const float4*>(&sKt[d*64 + ((4*tx) ^ ((d & 15) << 2))]);
                float bw[4] = {t.x, t.y, t.z, t.w};
                #pragma unroll
                for (int i = 0; i < 4; i++)
                    #pragma unroll
                    for (int j = 0; j < 4; j++)
                        s0[i][j] = fmaf(aq[i][u], bw[j], s0[i][j]);
            }
        }
        #pragma unroll 4
        for (int dd = 8; dd < 16; dd++) {
            float aq[4][4];
            #pragma unroll
            for (int i = 0; i < 4; i++) {
                float4 t = *reinterpret_cast<const float4*>(&sQ[(4*ty+i)*128 + dd*4]);
                aq[i][0]=t.x; aq[i][1]=t.y; aq[i][2]=t.z; aq[i][3]=t.w;
            }
            #pragma unroll
            for (int u = 0; u < 4; u++) {
                int d = dd*4 + u;
                float4 t = *reinterpret_cast<const float4*>(&sKt[d*64 + ((4*tx) ^ ((d & 15) << 2))]);
                float bw[4] = {t.x, t.y, t.z, t.w};
                #pragma unroll
                for (int i = 0; i < 4; i++)
                    #pragma unroll
                    for (int j = 0; j < 4; j++)
                        s1[i][j] = fmaf(aq[i][u], bw[j], s1[i][j]);
            }
        }
        #pragma unroll 4
        for (int dd = 16; dd < 32; dd++) {
            float aq[4][4];
            #pragma unroll
            for (int i = 0; i < 4; i++) {
                float4 t = *reinterpret_cast<const float4*>(&sQ[(4*ty+i)*128 + dd*4]);
                aq[i][0]=t.x; aq[i][1]=t.y; aq[i][2]=t.z; aq[i][3]=t.w;
            }
            #pragma unroll
            for (int u = 0; u < 4; u++) {
                int d = dd*4 + u;
                float4 t = *reinterpret_cast<const float4*>(&sKt[d*64 + ((4*tx) ^ ((d & 15) << 2))]);
                float bw[4] = {t.x, t.y, t.z, t.w};
                #pragma unroll
                for (int i = 0; i < 4; i++)
                    #pragma unroll
                    for (int j = 0; j < 4; j++)
                        s2[i][j] = fmaf(aq[i][u], bw[j], s2[i][j]);
            }
        }
        #pragma unroll
        for (int i = 0; i < 4; i++)
            #pragma unroll
            for (int j = 0; j < 4; j++) {
                s1[i][j] += s0[i][j];
                s2[i][j] += s1[i][j];
            }

        level_update<2>(s0, scale0, m_[0], l_[0], o0, q0, k0, ty, tx, sP, sV, 0);
        level_update<2>(s1, scale1, m_[1], l_[1], o1, q0, k0, ty, tx, sP, sV, 32);
        level_update<4>(s2, scale2, m_[2], l_[2], o2, q0, k0, ty, tx, sP, sV, 64);
    }

    // epilogue: normalize + write AO directly as bf16 hi/lo
    #pragma unroll
    for (int i = 0; i < 4; i++) {
        int qi = q0 + 4*ty + i;
        size_t base = ((size_t)(b*S_ + qi)) * (H_*DH_) + h*DH_;
        float i0 = 1.f / l_[0][i], i1 = 1.f / l_[1][i], i2 = 1.f / l_[2][i];
        float vals[8];
        int   offs[8];
        vals[0] = o0[i*2+0]*i0;  offs[0] = 2*tx;
        vals[1] = o0[i*2+1]*i0;  offs[1] = 2*tx+1;
        vals[2] = o1[i*2+0]*i1;  offs[2] = 32 + 2*tx;
        vals[3] = o1[i*2+1]*i1;  offs[3] = 32 + 2*tx+1;
        vals[4] = o2[i*4+0]*i2;  offs[4] = 64 + 4*tx;
        vals[5] = o2[i*4+1]*i2;  offs[5] = 64 + 4*tx+1;
        vals[6] = o2[i*4+2]*i2;  offs[6] = 64 + 4*tx+2;
        vals[7] = o2[i*4+3]*i2;  offs[7] = 64 + 4*tx+3;
        #pragma unroll
        for (int e = 0; e < 8; e++) {
            __nv_bfloat16 hh, ll;
            bf16_split(vals[e], hh, ll);
            g_AOh[base + offs[e]] = hh;
            g_AOl[base + offs[e]] = ll;
        }
    }
}

// ================= launch =================
extern "C" void kernel_launch(void* const* d_in, const int* in_sizes, int n_in,
                              void* d_out, int out_size)
{
    (void)in_sizes; (void)n_in; (void)out_size;
    const float* x  = (const float*)d_in[0];
    const float* Wq = (const float*)d_in[2];
    const float* bq = (const float*)d_in[3];
    const float* Wk = (const float*)d_in[4];
    const float* bk = (const float*)d_in[5];
    const float* Wv = (const float*)d_in[6];
    const float* bv = (const float*)d_in[7];
    const float* Wo = (const float*)d_in[8];
    const float* bo = (const float*)d_in[9];
    float* out = (float*)d_out;

    // converters
    convx_kernel<<<MROWS_*D_/4/256, 256>>>(x);
    tconv_qkv_kernel<<<dim3(NTOT_/64, D_/64), 256>>>(Wq, Wk, Wv);
    tconv_wo_kernel<<<dim3(D_/64, D_/64), 256>>>(Wo);

    // device-pointer lookups for __device__ arrays
    static __nv_bfloat16 *pxh=nullptr,*pxl,*pwth,*pwtl,*pwoth,*pwotl,*paoh,*paol;
    if (!pxh) {
        cudaGetSymbolAddress((void**)&pxh, g_xh);
        cudaGetSymbolAddress((void**)&pxl, g_xl);
        cudaGetSymbolAddress((void**)&pwth, g_Wth);
        cudaGetSymbolAddress((void**)&pwtl, g_Wtl);
        cudaGetSymbolAddress((void**)&pwoth, g_Woth);
        cudaGetSymbolAddress((void**)&pwotl, g_Wotl);
        cudaGetSymbolAddress((void**)&paoh, g_AOh);
        cudaGetSymbolAddress((void**)&paol, g_AOl);
    }

    const int gemm_smem = 2 * STAGE_B + 512;
    static bool attr_set = false;
    if (!attr_set) {
        cudaFuncSetAttribute(gemm_mma_kernel<0>, cudaFuncAttributeMaxDynamicSharedMemorySize, gemm_smem);
        cudaFuncSetAttribute(gemm_mma_kernel<1>, cudaFuncAttributeMaxDynamicSharedMemorySize, gemm_smem);
        size_t asm_sz = (size_t)(64*128 + 128*64 + 64*128 + 64*68) * sizeof(float);
        cudaFuncSetAttribute(attn_kernel, cudaFuncAttributeMaxDynamicSharedMemorySize, (int)asm_sz);
        attr_set = true;
    }

    // QKV GEMM (HMMA, bf16x3)
    gemm_mma_kernel<0><<<dim3(NTOT_/128, MROWS_/128), 256, gemm_smem>>>(
        pxh, pxl, pwth, pwtl, nullptr, bq, bk, bv);

    // attention
    size_t asm_sz = (size_t)(64*128 + 128*64 + 64*128 + 64*68) * sizeof(float);
    attn_kernel<<<dim3(S_/64, H_, B_), 256, asm_sz>>>();

    // output GEMM
    gemm_mma_kernel<1><<<dim3(D_/128, MROWS_/128), 256, gemm_smem>>>(
        paoh, paol, pwoth, pwotl, out, bo, nullptr, nullptr);
}

// round 5
// speedup vs baseline: 2.5636x; 1.3270x over previous
#include <cuda_runtime.h>
#include <cuda_bf16.h>
#include <stdint.h>
#include <cstdint>
#include <math.h>

#define B_ 2
#define S_ 1024
#define D_ 2048
#define H_ 16
#define G_ 4
#define DH_ 128
#define NQ_ 2048
#define NKV_ 512
#define NTOT_ 3072
#define MROWS_ 2048

// GEMM tiling
#define KC 32
#define PITCHB 80
#define TILE_B (128 * PITCHB)
#define STAGE_B (4 * TILE_B)

// Attention tiling
#define QT 128
#define KT 64
#define KPITCH 272
#define VPITCH 144
#define PPITCH 144
#define KTILE_AB (KT * KPITCH)            // 17408
#define VTILE_AB (DH_ * VPITCH)           // 18432
#define PTILE_AB (QT * PPITCH)            // 18432
#define STAGE_ATT (2*KTILE_AB + 2*VTILE_AB)   // 71680
#define P_OFF (2*STAGE_ATT)                    // 143360
#define ATT_SMEM (P_OFF + 2*PTILE_AB)          // 180224

#define SCALE0 0.17677669529663687f
#define SCALE1 0.125f
#define SCALE2 0.08838834764831843f

// ---------------- device scratch ----------------
__device__ __nv_bfloat16 g_xh[MROWS_*D_];
__device__ __nv_bfloat16 g_xl[MROWS_*D_];
__device__ __nv_bfloat16 g_Wth[NTOT_*D_];
__device__ __nv_bfloat16 g_Wtl[NTOT_*D_];
__device__ __nv_bfloat16 g_Woth[D_*D_];
__device__ __nv_bfloat16 g_Wotl[D_*D_];
__device__ __nv_bfloat16 g_AOh[MROWS_*D_];
__device__ __nv_bfloat16 g_AOl[MROWS_*D_];
__device__ __nv_bfloat16 g_Qh[B_*H_*S_*DH_];
__device__ __nv_bfloat16 g_Ql[B_*H_*S_*DH_];
__device__ __nv_bfloat16 g_Kh[B_*G_*S_*DH_];
__device__ __nv_bfloat16 g_Kl[B_*G_*S_*DH_];
__device__ __nv_bfloat16 g_Vth[B_*G_*DH_*S_];   // transposed [b,g,d,s]
__device__ __nv_bfloat16 g_Vtl[B_*G_*DH_*S_];

// ---------------- matryoshka reorder ----------------
__device__ __forceinline__ int perm16(int h, int d) {
    return (d < 32) ? (h*32 + d)
         : (d < 64) ? (512 + h*32 + (d-32))
                    : (1024 + h*64 + (d-64));
}
__device__ __forceinline__ int perm4(int g, int d) {
    return (d < 32) ? (g*32 + d)
         : (d < 64) ? (128 + g*32 + (d-32))
                    : (256 + g*64 + (d-64));
}

// ---------------- PTX helpers ----------------
__device__ __forceinline__ uint32_t smem_u32(const void* p) {
    uint32_t a;
    asm("{ .reg .u64 t; cvta.to.shared.u64 t, %1; cvt.u32.u64 %0, t; }" : "=r"(a) : "l"(p));
    return a;
}
__device__ __forceinline__ void cp_async16(uint32_t d, const void* g) {
    asm volatile("cp.async.cg.shared.global [%0], [%1], 16;" :: "r"(d), "l"(g));
}
__device__ __forceinline__ void ldsm4(uint32_t* r, uint32_t addr) {
    asm volatile("ldmatrix.sync.aligned.m8n8.x4.shared.b16 {%0,%1,%2,%3}, [%4];"
                 : "=r"(r[0]), "=r"(r[1]), "=r"(r[2]), "=r"(r[3]) : "r"(addr));
}
__device__ __forceinline__ void mma16816(float* c, const uint32_t* a, const uint32_t* b) {
    asm volatile(
        "mma.sync.aligned.m16n8k16.row.col.f32.bf16.bf16.f32 "
        "{%0,%1,%2,%3}, {%4,%5,%6,%7}, {%8,%9}, {%0,%1,%2,%3};"
        : "+f"(c[0]), "+f"(c[1]), "+f"(c[2]), "+f"(c[3])
        : "r"(a[0]), "r"(a[1]), "r"(a[2]), "r"(a[3]), "r"(b[0]), "r"(b[1]));
}
__device__ __forceinline__ void bf16_split(float v, __nv_bfloat16& h, __nv_bfloat16& l) {
    h = __float2bfloat16(v);
    l = __float2bfloat16(v - __bfloat162float(h));
}
// FMA-pipe exp (no MUFU): exp(x) = 2^(x*log2e), deg-5 poly, magic-number round
__device__ __forceinline__ float expf_fast(float x) {
    float t = x * 1.4426950408889634f;
    t = fminf(fmaxf(t, -60.f), 60.f);
    float z = t + 12582912.f;               // 1.5*2^23
    int   e = __float_as_int(z) - 0x4B400000;
    float r = z - 12582912.f;
    float f = t - r;
    float p = 1.3333558146428443e-3f;
    p = fmaf(p, f, 9.6181291076284772e-3f);
    p = fmaf(p, f, 5.5504108664821580e-2f);
    p = fmaf(p, f, 2.4022650695910071e-1f);
    p = fmaf(p, f, 6.9314718055994531e-1f);
    p = fmaf(p, f, 1.0f);
    return __int_as_float((e + 127) << 23) * p;
}

// ================= converters =================
__global__ __launch_bounds__(256) void convx_kernel(const float* __restrict__ x) {
    int i = blockIdx.x * 256 + threadIdx.x;
    float4 v = reinterpret_cast<const float4*>(x)[i];
    __nv_bfloat16 h0,l0,h1,l1,h2,l2,h3,l3;
    bf16_split(v.x,h0,l0); bf16_split(v.y,h1,l1); bf16_split(v.z,h2,l2); bf16_split(v.w,h3,l3);
    __nv_bfloat162* ph = reinterpret_cast<__nv_bfloat162*>(g_xh);
    __nv_bfloat162* pl = reinterpret_cast<__nv_bfloat162*>(g_xl);
    ph[2*i]   = __nv_bfloat162(h0,h1); ph[2*i+1] = __nv_bfloat162(h2,h3);
    pl[2*i]   = __nv_bfloat162(l0,l1); pl[2*i+1] = __nv_bfloat162(l2,l3);
}

__global__ __launch_bounds__(256)
void tconv_qkv_kernel(const float* __restrict__ Wq, const float* __restrict__ Wk,
                      const float* __restrict__ Wv) {
    __shared__ float ts[64][65];
    const int tid = threadIdx.x;
    const int n0 = blockIdx.x * 64, k0 = blockIdx.y * 64;
    for (int idx = tid; idx < 4096; idx += 256) {
        int kk = idx >> 6, nn = idx & 63;
        int n = n0 + nn;
        const float* W; int ldw, src;
        if (n < NQ_)            { W = Wq; ldw = NQ_;  src = perm16(n >> 7, n & 127); }
        else if (n < NQ_+NKV_)  { int t = n - NQ_;        W = Wk; ldw = NKV_; src = perm4(t >> 7, t & 127); }
        else                    { int t = n - NQ_ - NKV_; W = Wv; ldw = NKV_; src = perm4(t >> 7, t & 127); }
        ts[kk][nn] = W[(size_t)(k0 + kk) * ldw + src];
    }
    __syncthreads();
    for (int idx = tid; idx < 4096; idx += 256) {
        int nn = idx >> 6, kk = idx & 63;
        __nv_bfloat16 h, l;
        bf16_split(ts[kk][nn], h, l);
        size_t o = (size_t)(n0 + nn) * D_ + k0 + kk;
        g_Wth[o] = h; g_Wtl[o] = l;
    }
}

__global__ __launch_bounds__(256)
void tconv_wo_kernel(const float* __restrict__ Wo) {
    __shared__ float ts[64][65];
    const int tid = threadIdx.x;
    const int n0 = blockIdx.x * 64, k0 = blockIdx.y * 64;
    for (int idx = tid; idx < 4096; idx += 256) {
        int kk = idx >> 6, nn = idx & 63;
        int k = k0 + kk;
        int srcrow = perm16(k >> 7, k & 127);
        ts[kk][nn] = Wo[(size_t)srcrow * D_ + n0 + nn];
    }
    __syncthreads();
    for (int idx = tid; idx < 4096; idx += 256) {
        int nn = idx >> 6, kk = idx & 63;
        __nv_bfloat16 h, l;
        bf16_split(ts[kk][nn], h, l);
        size_t o = (size_t)(n0 + nn) * D_ + k0 + kk;
        g_Woth[o] = h; g_Wotl[o] = l;
    }
}

// ================= mma.sync bf16x3 GEMM =================
template<int MODE>
__global__ __launch_bounds__(256, 1)
void gemm_mma_kernel(const __nv_bfloat16* __restrict__ Ah, const __nv_bfloat16* __restrict__ Al,
                     const __nv_bfloat16* __restrict__ Bh, const __nv_bfloat16* __restrict__ Bl,
                     float* __restrict__ outp,
                     const float* __restrict__ bq, const float* __restrict__ bk,
                     const float* __restrict__ bv)
{
    extern __shared__ char smem[];
    const uint32_t sb = smem_u32(smem);
    float* sBias = reinterpret_cast<float*>(smem + 2 * STAGE_B);

    const int tid  = threadIdx.x;
    const int lane = tid & 31;
    const int wid  = tid >> 5;
    const int wm = wid >> 1;
    const int wn = wid & 1;
    const int n0 = blockIdx.x * 128;
    const int m0 = blockIdx.y * 128;
    const int NK = D_ / KC;

    if (tid < 128) {
        int n = n0 + tid;
        float b;
        if (MODE == 0) {
            if (n < NQ_)            b = bq[perm16(n >> 7, n & 127)];
            else if (n < NQ_+NKV_)  { int t = n - NQ_;        b = bk[perm4(t >> 7, t & 127)]; }
            else                    { int t = n - NQ_ - NKV_; b = bv[perm4(t >> 7, t & 127)]; }
        } else b = bq[n];
        sBias[tid] = b;
    }

    const __nv_bfloat16* srcs[4] = {
        Ah + (size_t)m0 * D_, Al + (size_t)m0 * D_,
        Bh + (size_t)n0 * D_, Bl + (size_t)n0 * D_ };

    auto load_stage = [&](int chunk) {
        const uint32_t st = sb + (chunk & 1) * STAGE_B;
        const int k0 = chunk * KC;
        #pragma unroll
        for (int t = 0; t < 4; t++) {
            const __nv_bfloat16* s = srcs[t];
            const uint32_t tb = st + t * TILE_B;
            #pragma unroll
            for (int it = 0; it < 2; it++) {
                int idx = tid + it * 256;
                int r = idx >> 2, c = idx & 3;
                cp_async16(tb + r * PITCHB + c * 16, s + (size_t)r * D_ + k0 + c * 8);
            }
        }
        asm volatile("cp.async.commit_group;" ::: "memory");
    };

    float acc[2][8][4];
    #pragma unroll
    for (int mi = 0; mi < 2; mi++)
        #pragma unroll
        for (int ni = 0; ni < 8; ni++)
            #pragma unroll
            for (int q = 0; q < 4; q++) acc[mi][ni][q] = 0.f;

    const int mat = lane >> 3, rin = lane & 7;
    const int arow = wm*32 + (mat & 1)*8 + rin;
    const uint32_t acol = (uint32_t)(mat >> 1) * 16;
    const int brow = wn*64 + (mat >> 1)*8 + rin;
    const uint32_t bcol = (uint32_t)(mat & 1) * 16;

    load_stage(0);
    load_stage(1);

    for (int i = 0; i < NK; i++) {
        if (i == NK - 1) asm volatile("cp.async.wait_group 0;" ::: "memory");
        else             asm volatile("cp.async.wait_group 1;" ::: "memory");
        __syncthreads();

        const uint32_t st = sb + (i & 1) * STAGE_B;
        const uint32_t aH = st, aL = st + TILE_B, bH = st + 2*TILE_B, bL = st + 3*TILE_B;

        #pragma unroll
        for (int kk = 0; kk < 2; kk++) {
            uint32_t ah[2][4], al[2][4];
            #pragma unroll
            for (int mi = 0; mi < 2; mi++) {
                uint32_t off = (uint32_t)(arow + mi*16) * PITCHB + acol + kk*32;
                ldsm4(ah[mi], aH + off);
                ldsm4(al[mi], aL + off);
            }
            uint32_t bhf[8][2], blf[8][2];
            #pragma unroll
            for (int nb = 0; nb < 4; nb++) {
                uint32_t off = (uint32_t)(brow + nb*16) * PITCHB + bcol + kk*32;
                uint32_t r4[4];
                ldsm4(r4, bH + off);
                bhf[2*nb][0] = r4[0]; bhf[2*nb][1] = r4[1];
                bhf[2*nb+1][0] = r4[2]; bhf[2*nb+1][1] = r4[3];
                ldsm4(r4, bL + off);
                blf[2*nb][0] = r4[0]; blf[2*nb][1] = r4[1];
                blf[2*nb+1][0] = r4[2]; blf[2*nb+1][1] = r4[3];
            }
            #pragma unroll
            for (int mi = 0; mi < 2; mi++)
                #pragma unroll
                for (int ni = 0; ni < 8; ni++) {
                    mma16816(acc[mi][ni], ah[mi], bhf[ni]);
                    mma16816(acc[mi][ni], al[mi], bhf[ni]);
                    mma16816(acc[mi][ni], ah[mi], blf[ni]);
                }
        }
        __syncthreads();
        if (i + 2 < NK) load_stage(i + 2);
    }

    // ---------- epilogue ----------
    const int g = lane >> 2, tig = lane & 3;
    #pragma unroll
    for (int mi = 0; mi < 2; mi++)
        #pragma unroll
        for (int ni = 0; ni < 8; ni++) {
            int col = wn*64 + ni*8 + tig*2;
            float b0 = sBias[col], b1 = sBias[col + 1];
            #pragma unroll
            for (int half = 0; half < 2; half++) {
                int row = m0 + wm*32 + mi*16 + g + half*8;
                float vx = acc[mi][ni][half*2+0] + b0;
                float vy = acc[mi][ni][half*2+1] + b1;
                if (MODE == 0) {
                    int bb = row >> 10, s = row & 1023;
                    __nv_bfloat16 hx,lx,hy,ly;
                    bf16_split(vx,hx,lx); bf16_split(vy,hy,ly);
                    if (n0 < NQ_) {
                        int h = n0 >> 7;
                        size_t o = ((size_t)((bb*H_ + h)*S_ + s))*DH_ + col;
                        *reinterpret_cast<__nv_bfloat162*>(g_Qh + o) = __nv_bfloat162(hx,hy);
                        *reinterpret_cast<__nv_bfloat162*>(g_Ql + o) = __nv_bfloat162(lx,ly);
                    } else if (n0 < NQ_+NKV_) {
                        int gg = (n0 - NQ_) >> 7;
                        size_t o = ((size_t)((bb*G_ + gg)*S_ + s))*DH_ + col;
                        *reinterpret_cast<__nv_bfloat162*>(g_Kh + o) = __nv_bfloat162(hx,hy);
                        *reinterpret_cast<__nv_bfloat162*>(g_Kl + o) = __nv_bfloat162(lx,ly);
                    } else {
                        int gg = (n0 - NQ_ - NKV_) >> 7;
                        size_t o = ((size_t)(bb*G_ + gg)*DH_ + col)*S_ + s;
                        g_Vth[o] = hx; g_Vtl[o] = lx;
                        g_Vth[o + S_] = hy; g_Vtl[o + S_] = ly;
                    }
                } else {
                    *reinterpret_cast<float2*>(outp + (size_t)row * D_ + n0 + col) =
                        make_float2(vx, vy);
                }
            }
        }
}

// ================= HMMA 3-level matryoshka flash attention =================
__global__ __launch_bounds__(256, 1)
void attn_mma_kernel()
{
    extern __shared__ char smem[];
    const uint32_t sb = smem_u32(smem);
    const int tid = threadIdx.x, lane = tid & 31, wid = tid >> 5;
    const int qt2 = (S_/QT - 1) - blockIdx.x;     // heavy CTAs first
    const int h = blockIdx.y, b = blockIdx.z, g = h >> 2;
    const int q0 = qt2 * QT;
    const int niter = 2*qt2 + 2;
    const int wq = wid * 16;
    const int mat = lane >> 3, rin = lane & 7;
    const int gq = lane >> 2, tig = lane & 3;

    const __nv_bfloat16* Khp = g_Kh + ((size_t)(b*G_ + g) * S_) * DH_;
    const __nv_bfloat16* Klp = g_Kl + ((size_t)(b*G_ + g) * S_) * DH_;
    const __nv_bfloat16* Vhp = g_Vth + (size_t)(b*G_ + g) * DH_ * S_;
    const __nv_bfloat16* Vlp = g_Vtl + (size_t)(b*G_ + g) * DH_ * S_;
    const __nv_bfloat16* Qhp = g_Qh + ((size_t)(b*H_ + h) * S_ + q0) * DH_;
    const __nv_bfloat16* Qlp = g_Ql + ((size_t)(b*H_ + h) * S_ + q0) * DH_;

    auto issue_kv = [&](int kt) {
        const uint32_t st = sb + (uint32_t)(kt & 1) * STAGE_ATT;
        const int k0 = kt * KT;
        #pragma unroll
        for (int i = 0; i < 4; i++) {
            int idx = tid + i * 256; int r = idx >> 4, c = idx & 15;
            cp_async16(st + r*KPITCH + c*16, Khp + (size_t)(k0 + r)*DH_ + c*8);
            cp_async16(st + KTILE_AB + r*KPITCH + c*16, Klp + (size_t)(k0 + r)*DH_ + c*8);
        }
        #pragma unroll
        for (int i = 0; i < 4; i++) {
            int idx = tid + i * 256; int r = idx >> 3, c = idx & 7;
            cp_async16(st + 2*KTILE_AB + r*VPITCH + c*16, Vhp + (size_t)r*S_ + k0 + c*8);
            cp_async16(st + 2*KTILE_AB + VTILE_AB + r*VPITCH + c*16, Vlp + (size_t)r*S_ + k0 + c*8);
        }
        asm volatile("cp.async.commit_group;" ::: "memory");
    };

    // prologue: stage Q into the stage-1 region, plus KV tile 0
    #pragma unroll
    for (int i = 0; i < 8; i++) {
        int idx = tid + i * 256; int r = idx >> 4, c = idx & 15;
        cp_async16(sb + STAGE_ATT + r*KPITCH + c*16, Qhp + (size_t)r*DH_ + c*8);
        cp_async16(sb + STAGE_ATT + 2*KTILE_AB + r*KPITCH + c*16, Qlp + (size_t)r*DH_ + c*8);
    }
    asm volatile("cp.async.commit_group;" ::: "memory");
    issue_kv(0);
    asm volatile("cp.async.wait_group 0;" ::: "memory");
    __syncthreads();

    // Q fragments resident in registers (all 8 k-steps, hi+lo)
    uint32_t qfh[8][4], qfl[8][4];
    {
        const uint32_t qb = sb + STAGE_ATT
            + (uint32_t)(wq + (mat & 1)*8 + rin) * KPITCH + (uint32_t)(mat >> 1) * 16;
        #pragma unroll
        for (int kk = 0; kk < 8; kk++) {
            ldsm4(qfh[kk], qb + kk*32);
            ldsm4(qfl[kk], qb + 2*KTILE_AB + kk*32);
        }
    }
    __syncthreads();

    float o0[4][4], o1[4][4], o2[8][4];
    float lsum[3][2] = {{0.f,0.f},{0.f,0.f},{0.f,0.f}};
    #pragma unroll
    for (int nb = 0; nb < 4; nb++)
        #pragma unroll
        for (int q = 0; q < 4; q++) { o0[nb][q] = 0.f; o1[nb][q] = 0.f; }
    #pragma unroll
    for (int nb = 0; nb < 8; nb++)
        #pragma unroll
        for (int q = 0; q < 4; q++) o2[nb][q] = 0.f;

    for (int kt = 0; kt < niter; kt++) {
        if (kt + 1 < niter) {
            issue_kv(kt + 1);
            asm volatile("cp.async.wait_group 1;" ::: "memory");
        } else {
            asm volatile("cp.async.wait_group 0;" ::: "memory");
        }
        __syncthreads();

        const uint32_t st = sb + (uint32_t)(kt & 1) * STAGE_ATT;
        const int k0 = kt * KT;
        const bool need_mask = (k0 + KT - 1 > q0 + wq);

        float acc[8][4];
        #pragma unroll
        for (int nb = 0; nb < 8; nb++)
            #pragma unroll
            for (int q = 0; q < 4; q++) acc[nb][q] = 0.f;

        const uint32_t kb = st + (uint32_t)((mat >> 1)*8 + rin) * KPITCH + (uint32_t)(mat & 1) * 16;

        auto do_level = [&](float scale, int dbase, float (*oacc)[4], float* ls, int nb2cnt) {
            const int r0g = q0 + wq + gq, r1g = r0g + 8;
            char* pbase = smem + P_OFF + (wq + gq)*PPITCH + tig*4;
            #pragma unroll
            for (int nb = 0; nb < 8; nb++) {
                int colg = k0 + nb*8 + tig*2;
                float p0 = expf_fast(acc[nb][0] * scale);
                float p1 = expf_fast(acc[nb][1] * scale);
                float p2 = expf_fast(acc[nb][2] * scale);
                float p3 = expf_fast(acc[nb][3] * scale);
                if (need_mask) {
                    if (colg     > r0g) p0 = 0.f;
                    if (colg + 1 > r0g) p1 = 0.f;
                    if (colg     > r1g) p2 = 0.f;
                    if (colg + 1 > r1g) p3 = 0.f;
                }
                ls[0] += p0 + p1; ls[1] += p2 + p3;
                __nv_bfloat16 h0,l0,h1,l1,h2,l2,h3,l3;
                bf16_split(p0,h0,l0); bf16_split(p1,h1,l1);
                bf16_split(p2,h2,l2); bf16_split(p3,h3,l3);
                char* pp = pbase + nb*16;
                *reinterpret_cast<__nv_bfloat162*>(pp)                        = __nv_bfloat162(h0,h1);
                *reinterpret_cast<__nv_bfloat162*>(pp + PTILE_AB)             = __nv_bfloat162(l0,l1);
                *reinterpret_cast<__nv_bfloat162*>(pp + 8*PPITCH)             = __nv_bfloat162(h2,h3);
                *reinterpret_cast<__nv_bfloat162*>(pp + 8*PPITCH + PTILE_AB)  = __nv_bfloat162(l2,l3);
            }
            __syncwarp();
            const uint32_t pa = sb + P_OFF
                + (uint32_t)(wq + (mat & 1)*8 + rin) * PPITCH + (uint32_t)(mat >> 1) * 16;
            #pragma unroll
            for (int kk2 = 0; kk2 < 4; kk2++) {
                uint32_t pah[4], pal[4];
                ldsm4(pah, pa + kk2*32);
                ldsm4(pal, pa + PTILE_AB + kk2*32);
                for (int nb2 = 0; nb2 < nb2cnt; nb2++) {
                    uint32_t voff = st + 2*KTILE_AB
                        + (uint32_t)(dbase + nb2*16 + (mat >> 1)*8 + rin) * VPITCH
                        + (uint32_t)(mat & 1)*16 + kk2*32;
                    uint32_t r4[4], s4[4];
                    ldsm4(r4, voff);
                    ldsm4(s4, voff + VTILE_AB);
                    uint32_t vh0[2] = {r4[0], r4[1]}, vh1[2] = {r4[2], r4[3]};
                    uint32_t vl0[2] = {s4[0], s4[1]}, vl1[2] = {s4[2], s4[3]};
                    mma16816(oacc[2*nb2],   pah, vh0);
                    mma16816(oacc[2*nb2],   pah, vl0);
                    mma16816(oacc[2*nb2],   pal, vh0);
                    mma16816(oacc[2*nb2+1], pah, vh1);
                    mma16816(oacc[2*nb2+1], pah, vl1);
                    mma16816(oacc[2*nb2+1], pal, vh1);
                }
            }
        };

        #pragma unroll
        for (int kk = 0; kk < 8; kk++) {
            uint32_t bh[8][2], bl[8][2];
            #pragma unroll
            for (int nb2 = 0; nb2 < 4; nb2++) {
                uint32_t r4[4];
                ldsm4(r4, kb + (uint32_t)(nb2*16)*KPITCH + kk*32);
                bh[2*nb2][0] = r4[0]; bh[2*nb2][1] = r4[1];
                bh[2*nb2+1][0] = r4[2]; bh[2*nb2+1][1] = r4[3];
                ldsm4(r4, kb + KTILE_AB + (uint32_t)(nb2*16)*KPITCH + kk*32);
                bl[2*nb2][0] = r4[0]; bl[2*nb2][1] = r4[1];
                bl[2*nb2+1][0] = r4[2]; bl[2*nb2+1][1] = r4[3];
            }
            #pragma unroll
            for (int nb = 0; nb < 8; nb++) {
                mma16816(acc[nb], qfh[kk], bh[nb]);
                mma16816(acc[nb], qfh[kk], bl[nb]);
                mma16816(acc[nb], qfl[kk], bh[nb]);
            }
            if (kk == 1) do_level(SCALE0, 0,  o0, lsum[0], 2);
            if (kk == 3) do_level(SCALE1, 32, o1, lsum[1], 2);
            if (kk == 7) do_level(SCALE2, 64, o2, lsum[2], 4);
        }
        __syncthreads();
    }

    // reduce row sums across the quad
    #pragma unroll
    for (int L = 0; L < 3; L++)
        #pragma unroll
        for (int j = 0; j < 2; j++) {
            lsum[L][j] += __shfl_xor_sync(0xffffffffu, lsum[L][j], 1);
            lsum[L][j] += __shfl_xor_sync(0xffffffffu, lsum[L][j], 2);
        }

    const int r0 = q0 + wq + gq;
    size_t base0 = ((size_t)(b*S_ + r0)) * D_ + (size_t)h * DH_;
    size_t base1 = base0 + 8 * (size_t)D_;
    auto store_pair = [&](size_t off, float a0, float a1) {
        __nv_bfloat16 ha, la, hb, lb;
        bf16_split(a0, ha, la); bf16_split(a1, hb, lb);
        *reinterpret_cast<__nv_bfloat162*>(g_AOh + off) = __nv_bfloat162(ha, hb);
        *reinterpret_cast<__nv_bfloat162*>(g_AOl + off) = __nv_bfloat162(la, lb);
    };
    float i00 = 1.f/lsum[0][0], i01 = 1.f/lsum[0][1];
    float i10 = 1.f/lsum[1][0], i11 = 1.f/lsum[1][1];
    float i20 = 1.f/lsum[2][0], i21 = 1.f/lsum[2][1];
    #pragma unroll
    for (int nb = 0; nb < 4; nb++) {
        int d = nb*8 + tig*2;
        store_pair(base0 + d,      o0[nb][0]*i00, o0[nb][1]*i00);
        store_pair(base1 + d,      o0[nb][2]*i01, o0[nb][3]*i01);
        store_pair(base0 + 32 + d, o1[nb][0]*i10, o1[nb][1]*i10);
        store_pair(base1 + 32 + d, o1[nb][2]*i11, o1[nb][3]*i11);
    }
    #pragma unroll
    for (int nb = 0; nb < 8; nb++) {
        int d = 64 + nb*8 + tig*2;
        store_pair(base0 + d, o2[nb][0]*i20, o2[nb][1]*i20);
        store_pair(base1 + d, o2[nb][2]*i21, o2[nb][3]*i21);
    }
}

// ================= launch =================
extern "C" void kernel_launch(void* const* d_in, const int* in_sizes, int n_in,
                              void* d_out, int out_size)
{
    (void)in_sizes; (void)n_in; (void)out_size;
    const float* x  = (const float*)d_in[0];
    const float* Wq = (const float*)d_in[2];
    const float* bq = (const float*)d_in[3];
    const float* Wk = (const float*)d_in[4];
    const float* bk = (const float*)d_in[5];
    const float* Wv = (const float*)d_in[6];
    const float* bv = (const float*)d_in[7];
    const float* Wo = (const float*)d_in[8];
    const float* bo = (const float*)d_in[9];
    float* out = (float*)d_out;

    convx_kernel<<<MROWS_*D_/4/256, 256>>>(x);
    tconv_qkv_kernel<<<dim3(NTOT_/64, D_/64), 256>>>(Wq, Wk, Wv);
    tconv_wo_kernel<<<dim3(D_/64, D_/64), 256>>>(Wo);

    static __nv_bfloat16 *pxh = nullptr, *pxl, *pwth, *pwtl, *pwoth, *pwotl, *paoh, *paol;
    if (!pxh) {
        cudaGetSymbolAddress((void**)&pxh, g_xh);
        cudaGetSymbolAddress((void**)&pxl, g_xl);
        cudaGetSymbolAddress((void**)&pwth, g_Wth);
        cudaGetSymbolAddress((void**)&pwtl, g_Wtl);
        cudaGetSymbolAddress((void**)&pwoth, g_Woth);
        cudaGetSymbolAddress((void**)&pwotl, g_Wotl);
        cudaGetSymbolAddress((void**)&paoh, g_AOh);
        cudaGetSymbolAddress((void**)&paol, g_AOl);
    }

    const int gemm_smem = 2 * STAGE_B + 512;
    static bool attr_set = false;
    if (!attr_set) {
        cudaFuncSetAttribute(gemm_mma_kernel<0>, cudaFuncAttributeMaxDynamicSharedMemorySize, gemm_smem);
        cudaFuncSetAttribute(gemm_mma_kernel<1>, cudaFuncAttributeMaxDynamicSharedMemorySize, gemm_smem);
        cudaFuncSetAttribute(attn_mma_kernel, cudaFuncAttributeMaxDynamicSharedMemorySize, ATT_SMEM);
        attr_set = true;
    }

    gemm_mma_kernel<0><<<dim3(NTOT_/128, MROWS_/128), 256, gemm_smem>>>(
        pxh, pxl, pwth, pwtl, nullptr, bq, bk, bv);

    attn_mma_kernel<<<dim3(S_/QT, H_, B_), 256, ATT_SMEM>>>();

    gemm_mma_kernel<1><<<dim3(D_/128, MROWS_/128), 256, gemm_smem>>>(
        paoh, paol, pwoth, pwotl, out, bo, nullptr, nullptr);
}

// round 6
// speedup vs baseline: 2.8760x; 1.1218x over previous
#include <cuda_runtime.h>
#include <cuda_bf16.h>
#include <stdint.h>
#include <cstdint>
#include <math.h>

#define B_ 2
#define S_ 1024
#define D_ 2048
#define H_ 16
#define G_ 4
#define DH_ 128
#define NQ_ 2048
#define NKV_ 512
#define NTOT_ 3072
#define MROWS_ 2048

// GEMM tiling
#define KC 32
#define PITCHB 80
#define TILE_B (128 * PITCHB)
#define STAGE_B (4 * TILE_B)

// Attention tiling
#define QT 128
#define KT 64
#define KPITCH 272
#define VPITCH 144
#define PPITCH 144
#define KTILE 17408                       // 64 * 272
#define VTILE 18432                       // 128 * 144
#define PTILE 18432                       // 128 * 144
#define V_OFF (2*KTILE)                   // 34816
#define Q_OFF (V_OFF + 4*VTILE)           // 108544
#define P_OFF (Q_OFF + 4*KTILE)           // 178176
#define LRED_OFF (P_OFF + 2*PTILE)        // 215040
#define ATT_SMEM (LRED_OFF + 3072)        // 218112

#define SCALE0 0.17677669529663687f
#define SCALE1 0.125f
#define SCALE2 0.08838834764831843f

// ---------------- device scratch ----------------
__device__ __nv_bfloat16 g_xh[MROWS_*D_];
__device__ __nv_bfloat16 g_xl[MROWS_*D_];
__device__ __nv_bfloat16 g_Wth[NTOT_*D_];
__device__ __nv_bfloat16 g_Wtl[NTOT_*D_];
__device__ __nv_bfloat16 g_Woth[D_*D_];
__device__ __nv_bfloat16 g_Wotl[D_*D_];
__device__ __nv_bfloat16 g_AOh[MROWS_*D_];
__device__ __nv_bfloat16 g_AOl[MROWS_*D_];
__device__ __nv_bfloat16 g_Qh[B_*H_*S_*DH_];
__device__ __nv_bfloat16 g_Ql[B_*H_*S_*DH_];
__device__ __nv_bfloat16 g_Kh[B_*G_*S_*DH_];
__device__ __nv_bfloat16 g_Kl[B_*G_*S_*DH_];
__device__ __nv_bfloat16 g_Vth[B_*G_*DH_*S_];   // [b,g,d,s]
__device__ __nv_bfloat16 g_Vtl[B_*G_*DH_*S_];

// ---------------- matryoshka reorder ----------------
__device__ __forceinline__ int perm16(int h, int d) {
    return (d < 32) ? (h*32 + d)
         : (d < 64) ? (512 + h*32 + (d-32))
                    : (1024 + h*64 + (d-64));
}
__device__ __forceinline__ int perm4(int g, int d) {
    return (d < 32) ? (g*32 + d)
         : (d < 64) ? (128 + g*32 + (d-32))
                    : (256 + g*64 + (d-64));
}

// ---------------- PTX helpers ----------------
__device__ __forceinline__ uint32_t smem_u32(const void* p) {
    uint32_t a;
    asm("{ .reg .u64 t; cvta.to.shared.u64 t, %1; cvt.u32.u64 %0, t; }" : "=r"(a) : "l"(p));
    return a;
}
__device__ __forceinline__ void cp_async16(uint32_t d, const void* g) {
    asm volatile("cp.async.cg.shared.global [%0], [%1], 16;" :: "r"(d), "l"(g));
}
__device__ __forceinline__ void ldsm4(uint32_t* r, uint32_t addr) {
    asm volatile("ldmatrix.sync.aligned.m8n8.x4.shared.b16 {%0,%1,%2,%3}, [%4];"
                 : "=r"(r[0]), "=r"(r[1]), "=r"(r[2]), "=r"(r[3]) : "r"(addr));
}
__device__ __forceinline__ void mma16816(float* c, const uint32_t* a, const uint32_t* b) {
    asm volatile(
        "mma.sync.aligned.m16n8k16.row.col.f32.bf16.bf16.f32 "
        "{%0,%1,%2,%3}, {%4,%5,%6,%7}, {%8,%9}, {%0,%1,%2,%3};"
        : "+f"(c[0]), "+f"(c[1]), "+f"(c[2]), "+f"(c[3])
        : "r"(a[0]), "r"(a[1]), "r"(a[2]), "r"(a[3]), "r"(b[0]), "r"(b[1]));
}
__device__ __forceinline__ void bf16_split(float v, __nv_bfloat16& h, __nv_bfloat16& l) {
    h = __float2bfloat16(v);
    l = __float2bfloat16(v - __bfloat162float(h));
}

// ================= converters =================
__global__ __launch_bounds__(256) void convx_kernel(const float* __restrict__ x) {
    int i = blockIdx.x * 256 + threadIdx.x;
    float4 v = reinterpret_cast<const float4*>(x)[i];
    __nv_bfloat16 h0,l0,h1,l1,h2,l2,h3,l3;
    bf16_split(v.x,h0,l0); bf16_split(v.y,h1,l1); bf16_split(v.z,h2,l2); bf16_split(v.w,h3,l3);
    __nv_bfloat162* ph = reinterpret_cast<__nv_bfloat162*>(g_xh);
    __nv_bfloat162* pl = reinterpret_cast<__nv_bfloat162*>(g_xl);
    ph[2*i]   = __nv_bfloat162(h0,h1); ph[2*i+1] = __nv_bfloat162(h2,h3);
    pl[2*i]   = __nv_bfloat162(l0,l1); pl[2*i+1] = __nv_bfloat162(l2,l3);
}

__global__ __launch_bounds__(256)
void tconv_qkv_kernel(const float* __restrict__ Wq, const float* __restrict__ Wk,
                      const float* __restrict__ Wv) {
    __shared__ float ts[64][65];
    const int tid = threadIdx.x;
    const int n0 = blockIdx.x * 64, k0 = blockIdx.y * 64;
    for (int idx = tid; idx < 4096; idx += 256) {
        int kk = idx >> 6, nn = idx & 63;
        int n = n0 + nn;
        const float* W; int ldw, src;
        if (n < NQ_)            { W = Wq; ldw = NQ_;  src = perm16(n >> 7, n & 127); }
        else if (n < NQ_+NKV_)  { int t = n - NQ_;        W = Wk; ldw = NKV_; src = perm4(t >> 7, t & 127); }
        else                    { int t = n - NQ_ - NKV_; W = Wv; ldw = NKV_; src = perm4(t >> 7, t & 127); }
        ts[kk][nn] = W[(size_t)(k0 + kk) * ldw + src];
    }
    __syncthreads();
    for (int idx = tid; idx < 4096; idx += 256) {
        int nn = idx >> 6, kk = idx & 63;
        __nv_bfloat16 h, l;
        bf16_split(ts[kk][nn], h, l);
        size_t o = (size_t)(n0 + nn) * D_ + k0 + kk;
        g_Wth[o] = h; g_Wtl[o] = l;
    }
}

__global__ __launch_bounds__(256)
void tconv_wo_kernel(const float* __restrict__ Wo) {
    __shared__ float ts[64][65];
    const int tid = threadIdx.x;
    const int n0 = blockIdx.x * 64, k0 = blockIdx.y * 64;
    for (int idx = tid; idx < 4096; idx += 256) {
        int kk = idx >> 6, nn = idx & 63;
        int k = k0 + kk;
        int srcrow = perm16(k >> 7, k & 127);
        ts[kk][nn] = Wo[(size_t)srcrow * D_ + n0 + nn];
    }
    __syncthreads();
    for (int idx = tid; idx < 4096; idx += 256) {
        int nn = idx >> 6, kk = idx & 63;
        __nv_bfloat16 h, l;
        bf16_split(ts[kk][nn], h, l);
        size_t o = (size_t)(n0 + nn) * D_ + k0 + kk;
        g_Woth[o] = h; g_Wotl[o] = l;
    }
}

// ================= mma.sync bf16x3 GEMM (2 CTAs/SM) =================
template<int MODE>
__global__ __launch_bounds__(256, 2)
void gemm_mma_kernel(const __nv_bfloat16* __restrict__ Ah, const __nv_bfloat16* __restrict__ Al,
                     const __nv_bfloat16* __restrict__ Bh, const __nv_bfloat16* __restrict__ Bl,
                     float* __restrict__ outp,
                     const float* __restrict__ bq, const float* __restrict__ bk,
                     const float* __restrict__ bv)
{
    extern __shared__ char smem[];
    const uint32_t sb = smem_u32(smem);
    float* sBias = reinterpret_cast<float*>(smem + 2 * STAGE_B);

    const int tid  = threadIdx.x;
    const int lane = tid & 31;
    const int wid  = tid >> 5;
    const int wm = wid >> 1;
    const int wn = wid & 1;
    const int n0 = blockIdx.x * 128;
    const int m0 = blockIdx.y * 128;
    const int NK = D_ / KC;

    if (tid < 128) {
        int n = n0 + tid;
        float b;
        if (MODE == 0) {
            if (n < NQ_)            b = bq[perm16(n >> 7, n & 127)];
            else if (n < NQ_+NKV_)  { int t = n - NQ_;        b = bk[perm4(t >> 7, t & 127)]; }
            else                    { int t = n - NQ_ - NKV_; b = bv[perm4(t >> 7, t & 127)]; }
        } else b = bq[n];
        sBias[tid] = b;
    }

    const __nv_bfloat16* srcs[4] = {
        Ah + (size_t)m0 * D_, Al + (size_t)m0 * D_,
        Bh + (size_t)n0 * D_, Bl + (size_t)n0 * D_ };

    auto load_stage = [&](int chunk) {
        const uint32_t st = sb + (chunk & 1) * STAGE_B;
        const int k0 = chunk * KC;
        #pragma unroll
        for (int t = 0; t < 4; t++) {
            const __nv_bfloat16* s = srcs[t];
            const uint32_t tb = st + t * TILE_B;
            #pragma unroll
            for (int it = 0; it < 2; it++) {
                int idx = tid + it * 256;
                int r = idx >> 2, c = idx & 3;
                cp_async16(tb + r * PITCHB + c * 16, s + (size_t)r * D_ + k0 + c * 8);
            }
        }
        asm volatile("cp.async.commit_group;" ::: "memory");
    };

    float acc[2][8][4];
    #pragma unroll
    for (int mi = 0; mi < 2; mi++)
        #pragma unroll
        for (int ni = 0; ni < 8; ni++)
            #pragma unroll
            for (int q = 0; q < 4; q++) acc[mi][ni][q] = 0.f;

    const int mat = lane >> 3, rin = lane & 7;
    const int arow = wm*32 + (mat & 1)*8 + rin;
    const uint32_t acol = (uint32_t)(mat >> 1) * 16;
    const int brow = wn*64 + (mat >> 1)*8 + rin;
    const uint32_t bcol = (uint32_t)(mat & 1) * 16;

    load_stage(0);
    load_stage(1);

    for (int i = 0; i < NK; i++) {
        if (i == NK - 1) asm volatile("cp.async.wait_group 0;" ::: "memory");
        else             asm volatile("cp.async.wait_group 1;" ::: "memory");
        __syncthreads();

        const uint32_t st = sb + (i & 1) * STAGE_B;
        const uint32_t aH = st, aL = st + TILE_B, bH = st + 2*TILE_B, bL = st + 3*TILE_B;

        #pragma unroll
        for (int kk = 0; kk < 2; kk++) {
            uint32_t ah[2][4], al[2][4];
            #pragma unroll
            for (int mi = 0; mi < 2; mi++) {
                uint32_t off = (uint32_t)(arow + mi*16) * PITCHB + acol + kk*32;
                ldsm4(ah[mi], aH + off);
                ldsm4(al[mi], aL + off);
            }
            #pragma unroll
            for (int half = 0; half < 2; half++) {
                uint32_t bhf[4][2], blf[4][2];
                #pragma unroll
                for (int nb2 = 0; nb2 < 2; nb2++) {
                    uint32_t off = (uint32_t)(brow + (half*2 + nb2)*16) * PITCHB + bcol + kk*32;
                    uint32_t r4[4];
                    ldsm4(r4, bH + off);
                    bhf[2*nb2][0] = r4[0]; bhf[2*nb2][1] = r4[1];
                    bhf[2*nb2+1][0] = r4[2]; bhf[2*nb2+1][1] = r4[3];
                    ldsm4(r4, bL + off);
                    blf[2*nb2][0] = r4[0]; blf[2*nb2][1] = r4[1];
                    blf[2*nb2+1][0] = r4[2]; blf[2*nb2+1][1] = r4[3];
                }
                #pragma unroll
                for (int mi = 0; mi < 2; mi++)
                    #pragma unroll
                    for (int nf = 0; nf < 4; nf++) {
                        int ni = half*4 + nf;
                        mma16816(acc[mi][ni], ah[mi], bhf[nf]);
                        mma16816(acc[mi][ni], al[mi], bhf[nf]);
                        mma16816(acc[mi][ni], ah[mi], blf[nf]);
                    }
            }
        }
        __syncthreads();
        if (i + 2 < NK) load_stage(i + 2);
    }

    // ---------- epilogue ----------
    const int g = lane >> 2, tig = lane & 3;
    #pragma unroll
    for (int mi = 0; mi < 2; mi++)
        #pragma unroll
        for (int ni = 0; ni < 8; ni++) {
            int col = wn*64 + ni*8 + tig*2;
            float b0 = sBias[col], b1 = sBias[col + 1];
            #pragma unroll
            for (int half = 0; half < 2; half++) {
                int row = m0 + wm*32 + mi*16 + g + half*8;
                float vx = acc[mi][ni][half*2+0] + b0;
                float vy = acc[mi][ni][half*2+1] + b1;
                if (MODE == 0) {
                    int bb = row >> 10, s = row & 1023;
                    __nv_bfloat16 hx,lx,hy,ly;
                    bf16_split(vx,hx,lx); bf16_split(vy,hy,ly);
                    if (n0 < NQ_) {
                        int h = n0 >> 7;
                        size_t o = ((size_t)((bb*H_ + h)*S_ + s))*DH_ + col;
                        *reinterpret_cast<__nv_bfloat162*>(g_Qh + o) = __nv_bfloat162(hx,hy);
                        *reinterpret_cast<__nv_bfloat162*>(g_Ql + o) = __nv_bfloat162(lx,ly);
                    } else if (n0 < NQ_+NKV_) {
                        int gg = (n0 - NQ_) >> 7;
                        size_t o = ((size_t)((bb*G_ + gg)*S_ + s))*DH_ + col;
                        *reinterpret_cast<__nv_bfloat162*>(g_Kh + o) = __nv_bfloat162(hx,hy);
                        *reinterpret_cast<__nv_bfloat162*>(g_Kl + o) = __nv_bfloat162(lx,ly);
                    } else {
                        int gg = (n0 - NQ_ - NKV_) >> 7;
                        size_t o = ((size_t)(bb*G_ + gg)*DH_ + col)*S_ + s;
                        g_Vth[o] = hx; g_Vtl[o] = lx;
                        g_Vth[o + S_] = hy; g_Vtl[o + S_] = ly;
                    }
                } else {
                    *reinterpret_cast<float2*>(outp + (size_t)row * D_ + n0 + col) =
                        make_float2(vx, vy);
                }
            }
        }
}

// ================= HMMA matryoshka flash attention (512 threads) =================
__global__ __launch_bounds__(512, 1)
void attn_mma_kernel()
{
    extern __shared__ char smem[];
    const uint32_t sb = smem_u32(smem);
    const int tid = threadIdx.x, lane = tid & 31, wid = tid >> 5;
    const int qt2 = (S_/QT - 1) - blockIdx.x;   // heavy CTAs first
    const int h = blockIdx.y, b = blockIdx.z, g = h >> 2;
    const int q0 = qt2 * QT;
    const int niter = 2*qt2 + 2;
    const int wq = (wid >> 1) * 16;             // q block (16 rows)
    const int wk = wid & 1;                     // k half (32 cols)
    const int mat = lane >> 3, rin = lane & 7;
    const int gq = lane >> 2, tig = lane & 3;

    const __nv_bfloat16* Khp = g_Kh + ((size_t)(b*G_ + g) * S_) * DH_;
    const __nv_bfloat16* Klp = g_Kl + ((size_t)(b*G_ + g) * S_) * DH_;
    const __nv_bfloat16* Vhp = g_Vth + (size_t)(b*G_ + g) * DH_ * S_;
    const __nv_bfloat16* Vlp = g_Vtl + (size_t)(b*G_ + g) * DH_ * S_;
    const __nv_bfloat16* Qhp = g_Qh + ((size_t)(b*H_ + h) * S_ + q0) * DH_;
    const __nv_bfloat16* Qlp = g_Ql + ((size_t)(b*H_ + h) * S_ + q0) * DH_;

    auto issue_K = [&](int kt) {
        const int k0 = kt * KT;
        #pragma unroll
        for (int i = 0; i < 2; i++) {
            int idx = tid + i * 512; int r = idx >> 4, c = idx & 15;
            cp_async16(sb + r*KPITCH + c*16, Khp + (size_t)(k0 + r)*DH_ + c*8);
            cp_async16(sb + KTILE + r*KPITCH + c*16, Klp + (size_t)(k0 + r)*DH_ + c*8);
        }
    };
    auto issue_V = [&](int kt) {
        const uint32_t st = sb + V_OFF + (uint32_t)(kt & 1) * (2*VTILE);
        const int k0 = kt * KT;
        #pragma unroll
        for (int i = 0; i < 2; i++) {
            int idx = tid + i * 512; int r = idx >> 3, c = idx & 7;
            cp_async16(st + r*VPITCH + c*16, Vhp + (size_t)r*S_ + k0 + c*8);
            cp_async16(st + VTILE + r*VPITCH + c*16, Vlp + (size_t)r*S_ + k0 + c*8);
        }
    };

    // prologue: Q persistent + K(0),V(0)
    #pragma unroll
    for (int i = 0; i < 4; i++) {
        int idx = tid + i * 512; int r = idx >> 4, c = idx & 15;
        cp_async16(sb + Q_OFF + r*KPITCH + c*16, Qhp + (size_t)r*DH_ + c*8);
        cp_async16(sb + Q_OFF + 2*KTILE + r*KPITCH + c*16, Qlp + (size_t)r*DH_ + c*8);
    }
    issue_K(0); issue_V(0);
    asm volatile("cp.async.commit_group;" ::: "memory");

    float o0[2][4] = {}, o1[2][4] = {}, o2[4][4] = {};
    float lsum[3][2] = {};

    const uint32_t qa  = sb + Q_OFF + (uint32_t)(wq + (mat & 1)*8 + rin) * KPITCH + (uint32_t)(mat >> 1) * 16;
    const uint32_t qal = qa + 2*KTILE;
    const uint32_t kbb = sb + (uint32_t)(wk*32 + (mat >> 1)*8 + rin) * KPITCH + (uint32_t)(mat & 1) * 16;
    const uint32_t pa  = sb + P_OFF + (uint32_t)(wq + (mat & 1)*8 + rin) * PPITCH + (uint32_t)(mat >> 1) * 16;
    char* pw = smem + P_OFF + (wq + gq)*PPITCH + wk*64 + tig*4;
    float* lred = reinterpret_cast<float*>(smem + LRED_OFF);

    for (int kt = 0; kt < niter; kt++) {
        asm volatile("cp.async.wait_group 0;" ::: "memory");
        __syncthreads();
        const int k0 = kt * KT;
        const uint32_t vst = sb + V_OFF + (uint32_t)(kt & 1) * (2*VTILE);

        float acc[4][4];
        #pragma unroll
        for (int nb = 0; nb < 4; nb++)
            #pragma unroll
            for (int q = 0; q < 4; q++) acc[nb][q] = 0.f;

        auto qk_steps = [&](int kkA, int kkB) {
            #pragma unroll
            for (int kk = kkA; kk < kkB; kk++) {
                uint32_t qh[4], ql[4];
                ldsm4(qh, qa + kk*32);
                ldsm4(ql, qal + kk*32);
                uint32_t bh[4][2], bl[4][2];
                #pragma unroll
                for (int nb2 = 0; nb2 < 2; nb2++) {
                    uint32_t r4[4];
                    ldsm4(r4, kbb + (uint32_t)(nb2*16)*KPITCH + kk*32);
                    bh[2*nb2][0] = r4[0]; bh[2*nb2][1] = r4[1];
                    bh[2*nb2+1][0] = r4[2]; bh[2*nb2+1][1] = r4[3];
                    ldsm4(r4, kbb + KTILE + (uint32_t)(nb2*16)*KPITCH + kk*32);
                    bl[2*nb2][0] = r4[0]; bl[2*nb2][1] = r4[1];
                    bl[2*nb2+1][0] = r4[2]; bl[2*nb2+1][1] = r4[3];
                }
                #pragma unroll
                for (int nb = 0; nb < 4; nb++) {
                    mma16816(acc[nb], qh, bh[nb]);
                    mma16816(acc[nb], qh, bl[nb]);
                    mma16816(acc[nb], ql, bh[nb]);
                }
            }
        };

        auto do_exp = [&](float scale, float* ls) {
            const int r0g = q0 + wq + gq, r1g = r0g + 8;
            const bool need_mask = (k0 + wk*32 + 31 > q0 + wq);
            #pragma unroll
            for (int nb = 0; nb < 4; nb++) {
                int colg = k0 + wk*32 + nb*8 + tig*2;
                float p0 = __expf(acc[nb][0] * scale);
                float p1 = __expf(acc[nb][1] * scale);
                float p2 = __expf(acc[nb][2] * scale);
                float p3 = __expf(acc[nb][3] * scale);
                if (need_mask) {
                    if (colg     > r0g) p0 = 0.f;
                    if (colg + 1 > r0g) p1 = 0.f;
                    if (colg     > r1g) p2 = 0.f;
                    if (colg + 1 > r1g) p3 = 0.f;
                }
                ls[0] += p0 + p1; ls[1] += p2 + p3;
                __nv_bfloat16 h0,l0,h1,l1,h2,l2,h3,l3;
                bf16_split(p0,h0,l0); bf16_split(p1,h1,l1);
                bf16_split(p2,h2,l2); bf16_split(p3,h3,l3);
                char* pp = pw + nb*16;
                *reinterpret_cast<__nv_bfloat162*>(pp)                      = __nv_bfloat162(h0,h1);
                *reinterpret_cast<__nv_bfloat162*>(pp + PTILE)              = __nv_bfloat162(l0,l1);
                *reinterpret_cast<__nv_bfloat162*>(pp + 8*PPITCH)           = __nv_bfloat162(h2,h3);
                *reinterpret_cast<__nv_bfloat162*>(pp + 8*PPITCH + PTILE)   = __nv_bfloat162(l2,l3);
            }
        };

        auto do_pv = [&](int dbase_w, float (*oacc)[4], int nb2cnt) {
            #pragma unroll
            for (int kk2 = 0; kk2 < 4; kk2++) {
                uint32_t pah[4], pal[4];
                ldsm4(pah, pa + kk2*32);
                ldsm4(pal, pa + PTILE + kk2*32);
                for (int nb2 = 0; nb2 < nb2cnt; nb2++) {
                    uint32_t voff = vst
                        + (uint32_t)(dbase_w + nb2*16 + (mat >> 1)*8 + rin) * VPITCH
                        + (uint32_t)(mat & 1)*16 + kk2*32;
                    uint32_t r4[4], s4[4];
                    ldsm4(r4, voff);
                    ldsm4(s4, voff + VTILE);
                    uint32_t vh0[2] = {r4[0], r4[1]}, vh1[2] = {r4[2], r4[3]};
                    uint32_t vl0[2] = {s4[0], s4[1]}, vl1[2] = {s4[2], s4[3]};
                    mma16816(oacc[2*nb2],   pah, vh0);
                    mma16816(oacc[2*nb2],   pah, vl0);
                    mma16816(oacc[2*nb2],   pal, vh0);
                    mma16816(oacc[2*nb2+1], pah, vh1);
                    mma16816(oacc[2*nb2+1], pah, vl1);
                    mma16816(oacc[2*nb2+1], pal, vh1);
                }
            }
        };

        qk_steps(0, 2);
        do_exp(SCALE0, lsum[0]);
        __syncthreads();
        do_pv(0 + wk*16, o0, 1);
        qk_steps(2, 4);
        __syncthreads();
        do_exp(SCALE1, lsum[1]);
        __syncthreads();
        do_pv(32 + wk*16, o1, 1);
        qk_steps(4, 8);
        __syncthreads();
        do_exp(SCALE2, lsum[2]);
        __syncthreads();
        if (kt + 1 < niter) { issue_K(kt + 1); issue_V(kt + 1); }
        asm volatile("cp.async.commit_group;" ::: "memory");
        do_pv(64 + wk*32, o2, 2);
    }

    // reduce row sums: quad (tig) via shfl, k-halves via smem
    #pragma unroll
    for (int L = 0; L < 3; L++)
        #pragma unroll
        for (int j = 0; j < 2; j++) {
            lsum[L][j] += __shfl_xor_sync(0xffffffffu, lsum[L][j], 1);
            lsum[L][j] += __shfl_xor_sync(0xffffffffu, lsum[L][j], 2);
        }
    __syncthreads();
    if (tig == 0) {
        #pragma unroll
        for (int L = 0; L < 3; L++) {
            lred[L*256 + (wq + gq)*2 + wk]     = lsum[L][0];
            lred[L*256 + (wq + gq + 8)*2 + wk] = lsum[L][1];
        }
    }
    __syncthreads();

    const int r0 = wq + gq, r1 = r0 + 8;
    float i00 = 1.f/(lred[0*256 + r0*2] + lred[0*256 + r0*2 + 1]);
    float i01 = 1.f/(lred[0*256 + r1*2] + lred[0*256 + r1*2 + 1]);
    float i10 = 1.f/(lred[1*256 + r0*2] + lred[1*256 + r0*2 + 1]);
    float i11 = 1.f/(lred[1*256 + r1*2] + lred[1*256 + r1*2 + 1]);
    float i20 = 1.f/(lred[2*256 + r0*2] + lred[2*256 + r0*2 + 1]);
    float i21 = 1.f/(lred[2*256 + r1*2] + lred[2*256 + r1*2 + 1]);

    size_t base0 = ((size_t)(b*S_ + q0 + r0)) * D_ + (size_t)h * DH_;
    size_t base1 = ((size_t)(b*S_ + q0 + r1)) * D_ + (size_t)h * DH_;
    auto store_pair = [&](size_t off, float a0, float a1) {
        __nv_bfloat16 ha, la, hb, lb;
        bf16_split(a0, ha, la); bf16_split(a1, hb, lb);
        *reinterpret_cast<__nv_bfloat162*>(g_AOh + off) = __nv_bfloat162(ha, hb);
        *reinterpret_cast<__nv_bfloat162*>(g_AOl + off) = __nv_bfloat162(la, lb);
    };
    #pragma unroll
    for (int j = 0; j < 2; j++) {
        int d = wk*16 + j*8 + tig*2;
        store_pair(base0 + d,      o0[j][0]*i00, o0[j][1]*i00);
        store_pair(base1 + d,      o0[j][2]*i01, o0[j][3]*i01);
        store_pair(base0 + 32 + d, o1[j][0]*i10, o1[j][1]*i10);
        store_pair(base1 + 32 + d, o1[j][2]*i11, o1[j][3]*i11);
    }
    #pragma unroll
    for (int j = 0; j < 4; j++) {
        int d = 64 + wk*32 + j*8 + tig*2;
        store_pair(base0 + d, o2[j][0]*i20, o2[j][1]*i20);
        store_pair(base1 + d, o2[j][2]*i21, o2[j][3]*i21);
    }
}

// ================= launch =================
extern "C" void kernel_launch(void* const* d_in, const int* in_sizes, int n_in,
                              void* d_out, int out_size)
{
    (void)in_sizes; (void)n_in; (void)out_size;
    const float* x  = (const float*)d_in[0];
    const float* Wq = (const float*)d_in[2];
    const float* bq = (const float*)d_in[3];
    const float* Wk = (const float*)d_in[4];
    const float* bk = (const float*)d_in[5];
    const float* Wv = (const float*)d_in[6];
    const float* bv = (const float*)d_in[7];
    const float* Wo = (const float*)d_in[8];
    const float* bo = (const float*)d_in[9];
    float* out = (float*)d_out;

    convx_kernel<<<MROWS_*D_/4/256, 256>>>(x);
    tconv_qkv_kernel<<<dim3(NTOT_/64, D_/64), 256>>>(Wq, Wk, Wv);
    tconv_wo_kernel<<<dim3(D_/64, D_/64), 256>>>(Wo);

    static __nv_bfloat16 *pxh = nullptr, *pxl, *pwth, *pwtl, *pwoth, *pwotl, *paoh, *paol;
    if (!pxh) {
        cudaGetSymbolAddress((void**)&pxh, g_xh);
        cudaGetSymbolAddress((void**)&pxl, g_xl);
        cudaGetSymbolAddress((void**)&pwth, g_Wth);
        cudaGetSymbolAddress((void**)&pwtl, g_Wtl);
        cudaGetSymbolAddress((void**)&pwoth, g_Woth);
        cudaGetSymbolAddress((void**)&pwotl, g_Wotl);
        cudaGetSymbolAddress((void**)&paoh, g_AOh);
        cudaGetSymbolAddress((void**)&paol, g_AOl);
    }

    const int gemm_smem = 2 * STAGE_B + 512;
    static bool attr_set = false;
    if (!attr_set) {
        cudaFuncSetAttribute(gemm_mma_kernel<0>, cudaFuncAttributeMaxDynamicSharedMemorySize, gemm_smem);
        cudaFuncSetAttribute(gemm_mma_kernel<1>, cudaFuncAttributeMaxDynamicSharedMemorySize, gemm_smem);
        cudaFuncSetAttribute(attn_mma_kernel, cudaFuncAttributeMaxDynamicSharedMemorySize, ATT_SMEM);
        attr_set = true;
    }

    gemm_mma_kernel<0><<<dim3(NTOT_/128, MROWS_/128), 256, gemm_smem>>>(
        pxh, pxl, pwth, pwtl, nullptr, bq, bk, bv);

    attn_mma_kernel<<<dim3(S_/QT, H_, B_), 512, ATT_SMEM>>>();

    gemm_mma_kernel<1><<<dim3(D_/128, MROWS_/128), 256, gemm_smem>>>(
        paoh, paol, pwoth, pwotl, out, bo, nullptr, nullptr);
}

// round 7
// speedup vs baseline: 3.2918x; 1.1446x over previous
#include <cuda_runtime.h>
#include <cuda_bf16.h>
#include <stdint.h>
#include <cstdint>
#include <math.h>

#define B_ 2
#define S_ 1024
#define D_ 2048
#define H_ 16
#define G_ 4
#define DH_ 128
#define NQ_ 2048
#define NKV_ 512
#define NTOT_ 3072
#define MROWS_ 2048

// GEMM tiling: KC=32, pitch 64 (swizzled), 3 stages
#define KC 32
#define TILE_GB 8192                    // 128 rows * 64B
#define STAGE_GB (4 * TILE_GB)          // Ah, Al, Bh, Bl = 32768
#define GEMM_SMEM (3 * STAGE_GB + 512)

// Attention tiling (all swizzled, unpadded)
#define QT 128
#define KT 64
#define QTILE 32768                     // 128 rows * 256B
#define KTILE 16384                     // 64 rows * 256B
#define VTILE 16384                     // 128 rows * 128B
#define PTILE 16384                     // 128 rows * 128B
#define K_OFF 65536
#define V_OFF 131072
#define P_OFF 196608
#define ATT_SMEM 229376

#define SCALE0 0.17677669529663687f
#define SCALE1 0.125f
#define SCALE2 0.08838834764831843f

// ---------------- device scratch ----------------
__device__ __nv_bfloat16 g_xh[MROWS_*D_];
__device__ __nv_bfloat16 g_xl[MROWS_*D_];
__device__ __nv_bfloat16 g_Wth[NTOT_*D_];
__device__ __nv_bfloat16 g_Wtl[NTOT_*D_];
__device__ __nv_bfloat16 g_Woth[D_*D_];
__device__ __nv_bfloat16 g_Wotl[D_*D_];
__device__ __nv_bfloat16 g_AOh[MROWS_*D_];
__device__ __nv_bfloat16 g_AOl[MROWS_*D_];
__device__ __nv_bfloat16 g_Qh[B_*H_*S_*DH_];
__device__ __nv_bfloat16 g_Ql[B_*H_*S_*DH_];
__device__ __nv_bfloat16 g_Kh[B_*G_*S_*DH_];
__device__ __nv_bfloat16 g_Kl[B_*G_*S_*DH_];
__device__ __nv_bfloat16 g_Vth[B_*G_*DH_*S_];   // [b,g,d,s]
__device__ __nv_bfloat16 g_Vtl[B_*G_*DH_*S_];

// ---------------- matryoshka reorder ----------------
__device__ __forceinline__ int perm16(int h, int d) {
    return (d < 32) ? (h*32 + d)
         : (d < 64) ? (512 + h*32 + (d-32))
                    : (1024 + h*64 + (d-64));
}
__device__ __forceinline__ int perm4(int g, int d) {
    return (d < 32) ? (g*32 + d)
         : (d < 64) ? (128 + g*32 + (d-32))
                    : (256 + g*64 + (d-64));
}

// ---------------- PTX helpers ----------------
__device__ __forceinline__ uint32_t smem_u32(const void* p) {
    uint32_t a;
    asm("{ .reg .u64 t; cvta.to.shared.u64 t, %1; cvt.u32.u64 %0, t; }" : "=r"(a) : "l"(p));
    return a;
}
__device__ __forceinline__ void cp_async16(uint32_t d, const void* g) {
    asm volatile("cp.async.cg.shared.global [%0], [%1], 16;" :: "r"(d), "l"(g));
}
__device__ __forceinline__ void ldsm4(uint32_t* r, uint32_t addr) {
    asm volatile("ldmatrix.sync.aligned.m8n8.x4.shared.b16 {%0,%1,%2,%3}, [%4];"
                 : "=r"(r[0]), "=r"(r[1]), "=r"(r[2]), "=r"(r[3]) : "r"(addr));
}
__device__ __forceinline__ void mma16816(float* c, const uint32_t* a, const uint32_t* b) {
    asm volatile(
        "mma.sync.aligned.m16n8k16.row.col.f32.bf16.bf16.f32 "
        "{%0,%1,%2,%3}, {%4,%5,%6,%7}, {%8,%9}, {%0,%1,%2,%3};"
        : "+f"(c[0]), "+f"(c[1]), "+f"(c[2]), "+f"(c[3])
        : "r"(a[0]), "r"(a[1]), "r"(a[2]), "r"(a[3]), "r"(b[0]), "r"(b[1]));
}
__device__ __forceinline__ void bar_pair(int id) {
    asm volatile("bar.sync %0, 64;" :: "r"(id) : "memory");
}
__device__ __forceinline__ void bf16_split(float v, __nv_bfloat16& h, __nv_bfloat16& l) {
    h = __float2bfloat16(v);
    l = __float2bfloat16(v - __bfloat162float(h));
}
// swizzled offsets (16B chunks)
__device__ __forceinline__ uint32_t swz64(int r, int c)  { return (uint32_t)r*64  + (uint32_t)((c ^ ((r>>1)&3)) << 4); }
__device__ __forceinline__ uint32_t swz128(int r, int c) { return (uint32_t)r*128 + (uint32_t)((c ^ (r&7)) << 4); }
__device__ __forceinline__ uint32_t swz256(int r, int c) { return (uint32_t)r*256 + (uint32_t)((c ^ (r&7)) << 4); }

// ================= converters =================
__global__ __launch_bounds__(256) void convx_kernel(const float* __restrict__ x) {
    int i = blockIdx.x * 256 + threadIdx.x;
    float4 v = reinterpret_cast<const float4*>(x)[i];
    __nv_bfloat16 h0,l0,h1,l1,h2,l2,h3,l3;
    bf16_split(v.x,h0,l0); bf16_split(v.y,h1,l1); bf16_split(v.z,h2,l2); bf16_split(v.w,h3,l3);
    __nv_bfloat162* ph = reinterpret_cast<__nv_bfloat162*>(g_xh);
    __nv_bfloat162* pl = reinterpret_cast<__nv_bfloat162*>(g_xl);
    ph[2*i]   = __nv_bfloat162(h0,h1); ph[2*i+1] = __nv_bfloat162(h2,h3);
    pl[2*i]   = __nv_bfloat162(l0,l1); pl[2*i+1] = __nv_bfloat162(l2,l3);
}

__global__ __launch_bounds__(256)
void tconv_qkv_kernel(const float* __restrict__ Wq, const float* __restrict__ Wk,
                      const float* __restrict__ Wv) {
    __shared__ float ts[64][65];
    const int tid = threadIdx.x;
    const int n0 = blockIdx.x * 64, k0 = blockIdx.y * 64;
    for (int idx = tid; idx < 4096; idx += 256) {
        int kk = idx >> 6, nn = idx & 63;
        int n = n0 + nn;
        const float* W; int ldw, src;
        if (n < NQ_)            { W = Wq; ldw = NQ_;  src = perm16(n >> 7, n & 127); }
        else if (n < NQ_+NKV_)  { int t = n - NQ_;        W = Wk; ldw = NKV_; src = perm4(t >> 7, t & 127); }
        else                    { int t = n - NQ_ - NKV_; W = Wv; ldw = NKV_; src = perm4(t >> 7, t & 127); }
        ts[kk][nn] = W[(size_t)(k0 + kk) * ldw + src];
    }
    __syncthreads();
    for (int idx = tid; idx < 4096; idx += 256) {
        int nn = idx >> 6, kk = idx & 63;
        __nv_bfloat16 h, l;
        bf16_split(ts[kk][nn], h, l);
        size_t o = (size_t)(n0 + nn) * D_ + k0 + kk;
        g_Wth[o] = h; g_Wtl[o] = l;
    }
}

__global__ __launch_bounds__(256)
void tconv_wo_kernel(const float* __restrict__ Wo) {
    __shared__ float ts[64][65];
    const int tid = threadIdx.x;
    const int n0 = blockIdx.x * 64, k0 = blockIdx.y * 64;
    for (int idx = tid; idx < 4096; idx += 256) {
        int kk = idx >> 6, nn = idx & 63;
        int k = k0 + kk;
        int srcrow = perm16(k >> 7, k & 127);
        ts[kk][nn] = Wo[(size_t)srcrow * D_ + n0 + nn];
    }
    __syncthreads();
    for (int idx = tid; idx < 4096; idx += 256) {
        int nn = idx >> 6, kk = idx & 63;
        __nv_bfloat16 h, l;
        bf16_split(ts[kk][nn], h, l);
        size_t o = (size_t)(n0 + nn) * D_ + k0 + kk;
        g_Woth[o] = h; g_Wotl[o] = l;
    }
}

// ================= mma.sync bf16x3 GEMM (3-stage, swizzled, 2 CTAs/SM) =================
template<int MODE>
__global__ __launch_bounds__(256, 2)
void gemm_mma_kernel(const __nv_bfloat16* __restrict__ Ah, const __nv_bfloat16* __restrict__ Al,
                     const __nv_bfloat16* __restrict__ Bh, const __nv_bfloat16* __restrict__ Bl,
                     float* __restrict__ outp,
                     const float* __restrict__ bq, const float* __restrict__ bk,
                     const float* __restrict__ bv)
{
    extern __shared__ char smem[];
    const uint32_t sb = smem_u32(smem);
    float* sBias = reinterpret_cast<float*>(smem + 3 * STAGE_GB);

    const int tid  = threadIdx.x;
    const int lane = tid & 31;
    const int wid  = tid >> 5;
    const int wm = wid >> 1;
    const int wn = wid & 1;
    const int n0 = blockIdx.x * 128;
    const int m0 = blockIdx.y * 128;
    const int NK = D_ / KC;     // 64

    if (tid < 128) {
        int n = n0 + tid;
        float b;
        if (MODE == 0) {
            if (n < NQ_)            b = bq[perm16(n >> 7, n & 127)];
            else if (n < NQ_+NKV_)  { int t = n - NQ_;        b = bk[perm4(t >> 7, t & 127)]; }
            else                    { int t = n - NQ_ - NKV_; b = bv[perm4(t >> 7, t & 127)]; }
        } else b = bq[n];
        sBias[tid] = b;
    }

    const __nv_bfloat16* srcs[4] = {
        Ah + (size_t)m0 * D_, Al + (size_t)m0 * D_,
        Bh + (size_t)n0 * D_, Bl + (size_t)n0 * D_ };

    // each thread loads 2 chunks/tile: idx = tid + it*256; r=idx>>2, c=idx&3
    auto load_stage = [&](int chunk) {
        const uint32_t st = sb + (uint32_t)(chunk % 3) * STAGE_GB;
        const int k0 = chunk * KC;
        #pragma unroll
        for (int t = 0; t < 4; t++) {
            const __nv_bfloat16* s = srcs[t];
            const uint32_t tb = st + t * TILE_GB;
            #pragma unroll
            for (int it = 0; it < 2; it++) {
                int idx = tid + it * 256;
                int r = idx >> 2, c = idx & 3;
                cp_async16(tb + swz64(r, c), s + (size_t)r * D_ + k0 + c * 8);
            }
        }
        asm volatile("cp.async.commit_group;" ::: "memory");
    };

    float acc[2][8][4];
    #pragma unroll
    for (int mi = 0; mi < 2; mi++)
        #pragma unroll
        for (int ni = 0; ni < 8; ni++)
            #pragma unroll
            for (int q = 0; q < 4; q++) acc[mi][ni][q] = 0.f;

    const int mat = lane >> 3, rin = lane & 7;
    const int arow = wm*32 + (mat & 1)*8 + rin;      // + mi*16
    const int acb  = (mat >> 1);                     // chunk bit for A
    const int brow = wn*64 + (mat >> 1)*8 + rin;     // + nb*16
    const int bcb  = (mat & 1);

    load_stage(0);
    load_stage(1);

    for (int i = 0; i < NK; i++) {
        if (i >= NK - 1) asm volatile("cp.async.wait_group 0;" ::: "memory");
        else             asm volatile("cp.async.wait_group 1;" ::: "memory");
        __syncthreads();
        if (i + 2 < NK) load_stage(i + 2);

        const uint32_t st = sb + (uint32_t)(i % 3) * STAGE_GB;
        const uint32_t aH = st, aL = st + TILE_GB, bH = st + 2*TILE_GB, bL = st + 3*TILE_GB;

        #pragma unroll
        for (int kk = 0; kk < 2; kk++) {
            uint32_t ah[2][4], al[2][4];
            #pragma unroll
            for (int mi = 0; mi < 2; mi++) {
                int r = arow + mi*16;
                uint32_t off = swz64(r, kk*2 + acb);
                ldsm4(ah[mi], aH + off);
                ldsm4(al[mi], aL + off);
            }
            #pragma unroll
            for (int half = 0; half < 2; half++) {
                uint32_t bhf[4][2], blf[4][2];
                #pragma unroll
                for (int nb2 = 0; nb2 < 2; nb2++) {
                    int r = brow + (half*2 + nb2)*16;
                    uint32_t off = swz64(r, kk*2 + bcb);
                    uint32_t r4[4];
                    ldsm4(r4, bH + off);
                    bhf[2*nb2][0] = r4[0]; bhf[2*nb2][1] = r4[1];
                    bhf[2*nb2+1][0] = r4[2]; bhf[2*nb2+1][1] = r4[3];
                    ldsm4(r4, bL + off);
                    blf[2*nb2][0] = r4[0]; blf[2*nb2][1] = r4[1];
                    blf[2*nb2+1][0] = r4[2]; blf[2*nb2+1][1] = r4[3];
                }
                #pragma unroll
                for (int mi = 0; mi < 2; mi++)
                    #pragma unroll
                    for (int nf = 0; nf < 4; nf++) {
                        int ni = half*4 + nf;
                        mma16816(acc[mi][ni], ah[mi], bhf[nf]);
                        mma16816(acc[mi][ni], al[mi], bhf[nf]);
                        mma16816(acc[mi][ni], ah[mi], blf[nf]);
                    }
            }
        }
    }

    // ---------- epilogue ----------
    const int g = lane >> 2, tig = lane & 3;
    #pragma unroll
    for (int mi = 0; mi < 2; mi++)
        #pragma unroll
        for (int ni = 0; ni < 8; ni++) {
            int col = wn*64 + ni*8 + tig*2;
            float b0 = sBias[col], b1 = sBias[col + 1];
            #pragma unroll
            for (int half = 0; half < 2; half++) {
                int row = m0 + wm*32 + mi*16 + g + half*8;
                float vx = acc[mi][ni][half*2+0] + b0;
                float vy = acc[mi][ni][half*2+1] + b1;
                if (MODE == 0) {
                    int bb = row >> 10, s = row & 1023;
                    __nv_bfloat16 hx,lx,hy,ly;
                    bf16_split(vx,hx,lx); bf16_split(vy,hy,ly);
                    if (n0 < NQ_) {
                        int h = n0 >> 7;
                        size_t o = ((size_t)((bb*H_ + h)*S_ + s))*DH_ + col;
                        *reinterpret_cast<__nv_bfloat162*>(g_Qh + o) = __nv_bfloat162(hx,hy);
                        *reinterpret_cast<__nv_bfloat162*>(g_Ql + o) = __nv_bfloat162(lx,ly);
                    } else if (n0 < NQ_+NKV_) {
                        int gg = (n0 - NQ_) >> 7;
                        size_t o = ((size_t)((bb*G_ + gg)*S_ + s))*DH_ + col;
                        *reinterpret_cast<__nv_bfloat162*>(g_Kh + o) = __nv_bfloat162(hx,hy);
                        *reinterpret_cast<__nv_bfloat162*>(g_Kl + o) = __nv_bfloat162(lx,ly);
                    } else {
                        int gg = (n0 - NQ_ - NKV_) >> 7;
                        size_t o = ((size_t)(bb*G_ + gg)*DH_ + col)*S_ + s;
                        g_Vth[o] = hx; g_Vtl[o] = lx;
                        g_Vth[o + S_] = hy; g_Vtl[o + S_] = ly;
                    }
                } else {
                    *reinterpret_cast<float2*>(outp + (size_t)row * D_ + n0 + col) =
                        make_float2(vx, vy);
                }
            }
        }
}

// ================= HMMA matryoshka flash attention (512 thr, pair barriers) =================
__global__ __launch_bounds__(512, 1)
void attn_mma_kernel()
{
    extern __shared__ char smem[];
    const uint32_t sb = smem_u32(smem);
    const int tid = threadIdx.x, lane = tid & 31, wid = tid >> 5;
    const int qt2 = (S_/QT - 1) - blockIdx.x;   // heavy CTAs first
    const int h = blockIdx.y, b = blockIdx.z, g = h >> 2;
    const int q0 = qt2 * QT;
    const int niter = 2*qt2 + 2;
    const int wq = (wid >> 1) * 16;
    const int wk = wid & 1;
    const int barid = 1 + (wid >> 1);           // pair barrier id 1..8
    const int mat = lane >> 3, rin = lane & 7;
    const int gq = lane >> 2, tig = lane & 3;

    const __nv_bfloat16* Khp = g_Kh + ((size_t)(b*G_ + g) * S_) * DH_;
    const __nv_bfloat16* Klp = g_Kl + ((size_t)(b*G_ + g) * S_) * DH_;
    const __nv_bfloat16* Vhp = g_Vth + (size_t)(b*G_ + g) * DH_ * S_;
    const __nv_bfloat16* Vlp = g_Vtl + (size_t)(b*G_ + g) * DH_ * S_;
    const __nv_bfloat16* Qhp = g_Qh + ((size_t)(b*H_ + h) * S_ + q0) * DH_;
    const __nv_bfloat16* Qlp = g_Ql + ((size_t)(b*H_ + h) * S_ + q0) * DH_;

    auto issue_KV = [&](int kt) {
        const uint32_t kst = sb + K_OFF + (uint32_t)(kt & 1) * (2*KTILE);
        const uint32_t vst = sb + V_OFF + (uint32_t)(kt & 1) * (2*VTILE);
        const int k0 = kt * KT;
        #pragma unroll
        for (int i = 0; i < 2; i++) {
            int idx = tid + i * 512;
            { int r = idx >> 4, c = idx & 15;
              cp_async16(kst + swz256(r, c), Khp + (size_t)(k0 + r)*DH_ + c*8);
              cp_async16(kst + KTILE + swz256(r, c), Klp + (size_t)(k0 + r)*DH_ + c*8); }
            { int r = idx >> 3, c = idx & 7;
              cp_async16(vst + swz128(r, c), Vhp + (size_t)r*S_ + k0 + c*8);
              cp_async16(vst + VTILE + swz128(r, c), Vlp + (size_t)r*S_ + k0 + c*8); }
        }
        asm volatile("cp.async.commit_group;" ::: "memory");
    };

    // prologue: Q persistent + K(0),V(0) in one group
    #pragma unroll
    for (int i = 0; i < 4; i++) {
        int idx = tid + i * 512; int r = idx >> 4, c = idx & 15;
        cp_async16(sb + swz256(r, c), Qhp + (size_t)r*DH_ + c*8);
        cp_async16(sb + QTILE + swz256(r, c), Qlp + (size_t)r*DH_ + c*8);
    }
    issue_KV(0);   // commits Q + KV0 together

    float o0[2][4] = {}, o1[2][4] = {}, o2[4][4] = {};
    float lsum[3][2] = {};

    const int rq = wq + (mat & 1)*8 + rin;          // Q/P fragment row
    const uint32_t qrow_off = (uint32_t)rq * 256;
    const int qsw = rq & 7;
    const uint32_t prow_off = (uint32_t)rq * 128;
    char* pwp = smem + P_OFF;                        // P write computed inline
    float* lred = reinterpret_cast<float*>(smem + P_OFF);  // aliased after loop

    for (int kt = 0; kt < niter; kt++) {
        asm volatile("cp.async.wait_group 0;" ::: "memory");
        __syncthreads();
        if (kt + 1 < niter) issue_KV(kt + 1);

        const int k0 = kt * KT;
        const uint32_t kst = sb + K_OFF + (uint32_t)(kt & 1) * (2*KTILE);
        const uint32_t vst = sb + V_OFF + (uint32_t)(kt & 1) * (2*VTILE);

        float acc[4][4];
        #pragma unroll
        for (int nb = 0; nb < 4; nb++)
            #pragma unroll
            for (int q = 0; q < 4; q++) acc[nb][q] = 0.f;

        auto qk_steps = [&](int kkA, int kkB) {
            #pragma unroll
            for (int kk = kkA; kk < kkB; kk++) {
                uint32_t qh[4], ql[4];
                uint32_t qoff = qrow_off + (uint32_t)(((kk*2 + (mat>>1)) ^ qsw) << 4);
                ldsm4(qh, sb + qoff);
                ldsm4(ql, sb + QTILE + qoff);
                uint32_t bh[4][2], bl[4][2];
                #pragma unroll
                for (int nb2 = 0; nb2 < 2; nb2++) {
                    int rk = wk*32 + nb2*16 + (mat >> 1)*8 + rin;
                    uint32_t off = swz256(rk, kk*2 + (mat & 1));
                    uint32_t r4[4];
                    ldsm4(r4, kst + off);
                    bh[2*nb2][0] = r4[0]; bh[2*nb2][1] = r4[1];
                    bh[2*nb2+1][0] = r4[2]; bh[2*nb2+1][1] = r4[3];
                    ldsm4(r4, kst + KTILE + off);
                    bl[2*nb2][0] = r4[0]; bl[2*nb2][1] = r4[1];
                    bl[2*nb2+1][0] = r4[2]; bl[2*nb2+1][1] = r4[3];
                }
                #pragma unroll
                for (int nb = 0; nb < 4; nb++) {
                    mma16816(acc[nb], qh, bh[nb]);
                    mma16816(acc[nb], qh, bl[nb]);
                    mma16816(acc[nb], ql, bh[nb]);
                }
            }
        };

        auto do_exp = [&](float scale, float* ls) {
            const int r0g = q0 + wq + gq, r1g = r0g + 8;
            const bool need_mask = (k0 + wk*32 + 31 > q0 + wq);
            #pragma unroll
            for (int nb = 0; nb < 4; nb++) {
                int colg = k0 + wk*32 + nb*8 + tig*2;
                float p0 = __expf(acc[nb][0] * scale);
                float p1 = __expf(acc[nb][1] * scale);
                float p2 = __expf(acc[nb][2] * scale);
                float p3 = __expf(acc[nb][3] * scale);
                if (need_mask) {
                    if (colg     > r0g) p0 = 0.f;
                    if (colg + 1 > r0g) p1 = 0.f;
                    if (colg     > r1g) p2 = 0.f;
                    if (colg + 1 > r1g) p3 = 0.f;
                }
                ls[0] += p0 + p1; ls[1] += p2 + p3;
                __nv_bfloat16 h0,l0,h1,l1,h2,l2,h3,l3;
                bf16_split(p0,h0,l0); bf16_split(p1,h1,l1);
                bf16_split(p2,h2,l2); bf16_split(p3,h3,l3);
                int rw0 = wq + gq, rw1 = rw0 + 8;
                int c = wk*4 + nb;
                uint32_t o0b = swz128(rw0, c) + tig*4;
                uint32_t o1b = swz128(rw1, c) + tig*4;
                *reinterpret_cast<__nv_bfloat162*>(pwp + o0b)          = __nv_bfloat162(h0,h1);
                *reinterpret_cast<__nv_bfloat162*>(pwp + o0b + PTILE)  = __nv_bfloat162(l0,l1);
                *reinterpret_cast<__nv_bfloat162*>(pwp + o1b)          = __nv_bfloat162(h2,h3);
                *reinterpret_cast<__nv_bfloat162*>(pwp + o1b + PTILE)  = __nv_bfloat162(l2,l3);
            }
        };

        auto do_pv = [&](int dbase, float (*oacc)[4], int nb2cnt) {
            #pragma unroll
            for (int kk2 = 0; kk2 < 4; kk2++) {
                uint32_t pah[4], pal[4];
                uint32_t poff = prow_off + (uint32_t)(((kk2*2 + (mat>>1)) ^ qsw) << 4);
                ldsm4(pah, sb + P_OFF + poff);
                ldsm4(pal, sb + P_OFF + PTILE + poff);
                for (int nb2 = 0; nb2 < nb2cnt; nb2++) {
                    int rv = dbase + nb2*16 + (mat >> 1)*8 + rin;
                    uint32_t voff = swz128(rv, kk2*2 + (mat & 1));
                    uint32_t r4[4], s4[4];
                    ldsm4(r4, vst + voff);
                    ldsm4(s4, vst + VTILE + voff);
                    uint32_t vh0[2] = {r4[0], r4[1]}, vh1[2] = {r4[2], r4[3]};
                    uint32_t vl0[2] = {s4[0], s4[1]}, vl1[2] = {s4[2], s4[3]};
                    mma16816(oacc[2*nb2],   pah, vh0);
                    mma16816(oacc[2*nb2],   pah, vl0);
                    mma16816(oacc[2*nb2],   pal, vh0);
                    mma16816(oacc[2*nb2+1], pah, vh1);
                    mma16816(oacc[2*nb2+1], pah, vl1);
                    mma16816(oacc[2*nb2+1], pal, vh1);
                }
            }
        };

        qk_steps(0, 2);
        do_exp(SCALE0, lsum[0]);
        bar_pair(barid);
        do_pv(0 + wk*16, o0, 1);
        qk_steps(2, 4);
        bar_pair(barid);
        do_exp(SCALE1, lsum[1]);
        bar_pair(barid);
        do_pv(32 + wk*16, o1, 1);
        qk_steps(4, 8);
        bar_pair(barid);
        do_exp(SCALE2, lsum[2]);
        bar_pair(barid);
        do_pv(64 + wk*32, o2, 2);
    }

    // reduce row sums: quad via shfl, k-halves via smem (lred aliases P)
    #pragma unroll
    for (int L = 0; L < 3; L++)
        #pragma unroll
        for (int j = 0; j < 2; j++) {
            lsum[L][j] += __shfl_xor_sync(0xffffffffu, lsum[L][j], 1);
            lsum[L][j] += __shfl_xor_sync(0xffffffffu, lsum[L][j], 2);
        }
    __syncthreads();
    if (tig == 0) {
        #pragma unroll
        for (int L = 0; L < 3; L++) {
            lred[L*256 + (wq + gq)*2 + wk]     = lsum[L][0];
            lred[L*256 + (wq + gq + 8)*2 + wk] = lsum[L][1];
        }
    }
    __syncthreads();

    const int r0 = wq + gq, r1 = r0 + 8;
    float i00 = 1.f/(lred[0*256 + r0*2] + lred[0*256 + r0*2 + 1]);
    float i01 = 1.f/(lred[0*256 + r1*2] + lred[0*256 + r1*2 + 1]);
    float i10 = 1.f/(lred[1*256 + r0*2] + lred[1*256 + r0*2 + 1]);
    float i11 = 1.f/(lred[1*256 + r1*2] + lred[1*256 + r1*2 + 1]);
    float i20 = 1.f/(lred[2*256 + r0*2] + lred[2*256 + r0*2 + 1]);
    float i21 = 1.f/(lred[2*256 + r1*2] + lred[2*256 + r1*2 + 1]);

    size_t base0 = ((size_t)(b*S_ + q0 + r0)) * D_ + (size_t)h * DH_;
    size_t base1 = ((size_t)(b*S_ + q0 + r1)) * D_ + (size_t)h * DH_;
    auto store_pair = [&](size_t off, float a0, float a1) {
        __nv_bfloat16 ha, la, hb, lb;
        bf16_split(a0, ha, la); bf16_split(a1, hb, lb);
        *reinterpret_cast<__nv_bfloat162*>(g_AOh + off) = __nv_bfloat162(ha, hb);
        *reinterpret_cast<__nv_bfloat162*>(g_AOl + off) = __nv_bfloat162(la, lb);
    };
    #pragma unroll
    for (int j = 0; j < 2; j++) {
        int d = wk*16 + j*8 + tig*2;
        store_pair(base0 + d,      o0[j][0]*i00, o0[j][1]*i00);
        store_pair(base1 + d,      o0[j][2]*i01, o0[j][3]*i01);
        store_pair(base0 + 32 + d, o1[j][0]*i10, o1[j][1]*i10);
        store_pair(base1 + 32 + d, o1[j][2]*i11, o1[j][3]*i11);
    }
    #pragma unroll
    for (int j = 0; j < 4; j++) {
        int d = 64 + wk*32 + j*8 + tig*2;
        store_pair(base0 + d, o2[j][0]*i20, o2[j][1]*i20);
        store_pair(base1 + d, o2[j][2]*i21, o2[j][3]*i21);
    }
}

// ================= launch =================
extern "C" void kernel_launch(void* const* d_in, const int* in_sizes, int n_in,
                              void* d_out, int out_size)
{
    (void)in_sizes; (void)n_in; (void)out_size;
    const float* x  = (const float*)d_in[0];
    const float* Wq = (const float*)d_in[2];
    const float* bq = (const float*)d_in[3];
    const float* Wk = (const float*)d_in[4];
    const float* bk = (const float*)d_in[5];
    const float* Wv = (const float*)d_in[6];
    const float* bv = (const float*)d_in[7];
    const float* Wo = (const float*)d_in[8];
    const float* bo = (const float*)d_in[9];
    float* out = (float*)d_out;

    convx_kernel<<<MROWS_*D_/4/256, 256>>>(x);
    tconv_qkv_kernel<<<dim3(NTOT_/64, D_/64), 256>>>(Wq, Wk, Wv);
    tconv_wo_kernel<<<dim3(D_/64, D_/64), 256>>>(Wo);

    static __nv_bfloat16 *pxh = nullptr, *pxl, *pwth, *pwtl, *pwoth, *pwotl, *paoh, *paol;
    if (!pxh) {
        cudaGetSymbolAddress((void**)&pxh, g_xh);
        cudaGetSymbolAddress((void**)&pxl, g_xl);
        cudaGetSymbolAddress((void**)&pwth, g_Wth);
        cudaGetSymbolAddress((void**)&pwtl, g_Wtl);
        cudaGetSymbolAddress((void**)&pwoth, g_Woth);
        cudaGetSymbolAddress((void**)&pwotl, g_Wotl);
        cudaGetSymbolAddress((void**)&paoh, g_AOh);
        cudaGetSymbolAddress((void**)&paol, g_AOl);
    }

    static bool attr_set = false;
    if (!attr_set) {
        cudaFuncSetAttribute(gemm_mma_kernel<0>, cudaFuncAttributeMaxDynamicSharedMemorySize, GEMM_SMEM);
        cudaFuncSetAttribute(gemm_mma_kernel<1>, cudaFuncAttributeMaxDynamicSharedMemorySize, GEMM_SMEM);
        cudaFuncSetAttribute(attn_mma_kernel, cudaFuncAttributeMaxDynamicSharedMemorySize, ATT_SMEM);
        attr_set = true;
    }

    gemm_mma_kernel<0><<<dim3(NTOT_/128, MROWS_/128), 256, GEMM_SMEM>>>(
        pxh, pxl, pwth, pwtl, nullptr, bq, bk, bv);

    attn_mma_kernel<<<dim3(S_/QT, H_, B_), 512, ATT_SMEM>>>();

    gemm_mma_kernel<1><<<dim3(D_/128, MROWS_/128), 256, GEMM_SMEM>>>(
        paoh, paol, pwoth, pwotl, out, bo, nullptr, nullptr);
}